// round 5
// baseline (speedup 1.0000x reference)
#include <cuda_runtime.h>
#include <math.h>
#include <stdint.h>

#define BB 4
#define SS 2048
#define HH 1024
#define INNERD 512
#define RAD 8
#define KSTEPS 4
#define LAMv 0.1f
#define MU_MAXV 10.0f

#define BSH (BB*SS*HH)

// Scratch (no cudaMalloc allowed). Ping-pong state buffers.
__device__ float g_q[BSH];
__device__ float g_stateA[BSH];
__device__ float g_stateB[BSH];
__device__ float g_nsq[BB*SS];
__device__ float g_dots[BB*RAD*SS];
__device__ float g_mu[BB*RAD*SS];
__device__ float g_isq[BB*SS];

__device__ __forceinline__ float to_tf32(float x) {
    float r;
    asm("cvt.rna.tf32.f32 %0, %1;" : "=f"(r) : "f"(x));
    return r;
}

// ---------------------------------------------------------------------------
// GEMM (TF32 mma.sync): q = hidden @ Wq + bq.  M=8192, N=K=1024.
// Block 128x128, 8 warps, warp 32x64, K-step 32.  (R2 version, measured good.)
// ---------------------------------------------------------------------------
#define TM 128
#define TN 128
#define TK 32

__global__ __launch_bounds__(256) void gemm_tf32_kernel(
    const float* __restrict__ A,
    const float* __restrict__ W,
    const float* __restrict__ bias)
{
    const int N = HH, K = HH;
    __shared__ float As[TK][TM + 4];   // k-major
    __shared__ float Bs[TK][TN + 4];

    int tid = threadIdx.x;
    int m0 = blockIdx.y * TM;
    int n0 = blockIdx.x * TN;
    int wid = tid >> 5, lane = tid & 31;
    int wm = (wid & 3) * 32;
    int wn = (wid >> 2) * 64;
    int gid = lane >> 2, tig = lane & 3;

    float acc[2][8][4];
#pragma unroll
    for (int mt = 0; mt < 2; mt++)
#pragma unroll
        for (int nt = 0; nt < 8; nt++)
#pragma unroll
            for (int c = 0; c < 4; c++) acc[mt][nt][c] = 0.f;

    int a_row = tid >> 3;            // 0..31
    int a_k4  = (tid & 7) * 4;       // 0..28
    int b_k   = tid >> 5;            // 0..7
    int b_n4  = (tid & 31) * 4;      // 0..124

    for (int k0 = 0; k0 < K; k0 += TK) {
        __syncthreads();
#pragma unroll
        for (int r = 0; r < 4; r++) {
            int m = a_row + r * 32;
            float4 v = *(const float4*)&A[(size_t)(m0 + m) * K + k0 + a_k4];
            As[a_k4 + 0][m] = to_tf32(v.x);
            As[a_k4 + 1][m] = to_tf32(v.y);
            As[a_k4 + 2][m] = to_tf32(v.z);
            As[a_k4 + 3][m] = to_tf32(v.w);
        }
#pragma unroll
        for (int r = 0; r < 4; r++) {
            int k = b_k + r * 8;
            float4 v = *(const float4*)&W[(size_t)(k0 + k) * N + n0 + b_n4];
            Bs[k][b_n4 + 0] = to_tf32(v.x);
            Bs[k][b_n4 + 1] = to_tf32(v.y);
            Bs[k][b_n4 + 2] = to_tf32(v.z);
            Bs[k][b_n4 + 3] = to_tf32(v.w);
        }
        __syncthreads();

#pragma unroll
        for (int ks = 0; ks < 4; ks++) {
            int kb = ks * 8;
            uint32_t af[2][4];
#pragma unroll
            for (int mt = 0; mt < 2; mt++) {
                int rm = wm + mt * 16 + gid;
                af[mt][0] = __float_as_uint(As[kb + tig][rm]);
                af[mt][1] = __float_as_uint(As[kb + tig][rm + 8]);
                af[mt][2] = __float_as_uint(As[kb + tig + 4][rm]);
                af[mt][3] = __float_as_uint(As[kb + tig + 4][rm + 8]);
            }
            uint32_t bf[8][2];
#pragma unroll
            for (int nt = 0; nt < 8; nt++) {
                int cn = wn + nt * 8 + gid;
                bf[nt][0] = __float_as_uint(Bs[kb + tig][cn]);
                bf[nt][1] = __float_as_uint(Bs[kb + tig + 4][cn]);
            }
#pragma unroll
            for (int mt = 0; mt < 2; mt++)
#pragma unroll
                for (int nt = 0; nt < 8; nt++) {
                    asm volatile(
                        "mma.sync.aligned.m16n8k8.row.col.f32.tf32.tf32.f32 "
                        "{%0,%1,%2,%3}, {%4,%5,%6,%7}, {%8,%9}, {%0,%1,%2,%3};"
                        : "+f"(acc[mt][nt][0]), "+f"(acc[mt][nt][1]),
                          "+f"(acc[mt][nt][2]), "+f"(acc[mt][nt][3])
                        : "r"(af[mt][0]), "r"(af[mt][1]),
                          "r"(af[mt][2]), "r"(af[mt][3]),
                          "r"(bf[nt][0]), "r"(bf[nt][1]));
                }
        }
    }

#pragma unroll
    for (int mt = 0; mt < 2; mt++) {
        int row0 = m0 + wm + mt * 16 + gid;
#pragma unroll
        for (int nt = 0; nt < 8; nt++) {
            int col = n0 + wn + nt * 8 + 2 * tig;
            float bx = bias[col], by = bias[col + 1];
            float2 v0 = make_float2(acc[mt][nt][0] + bx, acc[mt][nt][1] + by);
            float2 v1 = make_float2(acc[mt][nt][2] + bx, acc[mt][nt][3] + by);
            *(float2*)&g_q[(size_t)row0 * N + col] = v0;
            *(float2*)&g_q[(size_t)(row0 + 8) * N + col] = v1;
        }
    }
}

// ---------------------------------------------------------------------------
// Tiled dots (R2 version + src param): block = 24 nodes (+8 halo rows).
// ---------------------------------------------------------------------------
#define DT 24
#define DROWS 32
#define DOTS_SMEM (DROWS * HH * sizeof(float))

__global__ __launch_bounds__(256) void dots_tiled_kernel(const float* __restrict__ src)
{
    extern __shared__ float sh[];  // DROWS * HH
    int tid = threadIdx.x;
    int b = blockIdx.y;
    int i0 = blockIdx.x * DT;

#pragma unroll
    for (int r = 0; r < DROWS; r++) {
        int i = i0 + r;
        if (i < SS)
            ((float4*)(sh + (size_t)r * HH))[tid] =
                ((const float4*)(src + ((size_t)b * SS + i) * HH))[tid];
    }
    __syncthreads();

    int w = tid >> 5, lane = tid & 31;
#pragma unroll
    for (int nn = 0; nn < 3; nn++) {
        int ln = w * 3 + nn;          // 0..23
        int i = i0 + ln;
        if (i >= SS) continue;
        const float4* arow = (const float4*)(sh + (size_t)ln * HH);
        float4 a[8];
#pragma unroll
        for (int r = 0; r < 8; r++) a[r] = arow[lane + 32 * r];

#pragma unroll
        for (int d = 0; d <= RAD; d++) {
            if (d > 0 && i + d >= SS) break;
            float sum = 0.f;
            if (d == 0) {
#pragma unroll
                for (int r = 0; r < 8; r++)
                    sum += a[r].x*a[r].x + a[r].y*a[r].y + a[r].z*a[r].z + a[r].w*a[r].w;
            } else {
                const float4* crow = (const float4*)(sh + (size_t)(ln + d) * HH);
#pragma unroll
                for (int r = 0; r < 8; r++) {
                    float4 c = crow[lane + 32 * r];
                    sum += a[r].x*c.x + a[r].y*c.y + a[r].z*c.z + a[r].w*c.w;
                }
            }
#pragma unroll
            for (int o = 16; o > 0; o >>= 1)
                sum += __shfl_xor_sync(0xffffffffu, sum, o);
            if (lane == 0) {
                if (d == 0) g_nsq[b * SS + i] = sum;
                else g_dots[((size_t)b * RAD + (d - 1)) * SS + i] = sum;
            }
        }
    }
}

// ---------------------------------------------------------------------------
// mu: 8 threads per edge (64 channels each), weights in smem, GELU fast-path.
// (R3 version — the one evidence-backed improvement: occ 21% -> ~full.)
// ---------------------------------------------------------------------------
__global__ __launch_bounds__(256) void mu_kernel3(
    const float* __restrict__ W1, const float* __restrict__ b1,
    const float* __restrict__ W2, const float* __restrict__ b2)
{
    __shared__ float w1a[INNERD], w1b[INNERD], bb1[INNERD], w2s[INNERD];
    int tid = threadIdx.x;
#pragma unroll
    for (int r = 0; r < 2; r++) {
        int k = tid + 256 * r;
        w1a[k] = W1[k];
        w1b[k] = W1[INNERD + k];
        bb1[k] = b1[k];
        w2s[k] = W2[k];
    }
    __syncthreads();

    int e = blockIdx.x * 32 + (tid >> 3);     // edge id
    int sub = tid & 7;
    int b = e >> 14;
    int r = e & 16383;
    int d = (r >> 11) + 1;
    int i = r & 2047;
    size_t slot = ((size_t)b * RAD + (d - 1)) * SS + i;
    bool valid = (i + d < SS);

    int j = valid ? (i + d) : i;
    float nsqi = g_nsq[b * SS + i];
    float nsqj = g_nsq[b * SS + j];
    float dot  = valid ? g_dots[slot] : 0.f;
    float dist = sqrtf(fmaxf(nsqi + nsqj - 2.f * dot, 0.f));
    float ni = fmaxf(sqrtf(nsqi), 1e-6f);
    float nj = fmaxf(sqrtf(nsqj), 1e-6f);
    float cosv = dot / (ni * nj);

    float z = 0.f;
    int kbase = sub * 64;
#pragma unroll 4
    for (int k = kbase; k < kbase + 64; k += 4) {
        float4 wa = *(const float4*)&w1a[k];
        float4 wb = *(const float4*)&w1b[k];
        float4 bv = *(const float4*)&bb1[k];
        float4 w2v = *(const float4*)&w2s[k];
        float x0 = fmaf(dist, wa.x, fmaf(cosv, wb.x, bv.x));
        float x1 = fmaf(dist, wa.y, fmaf(cosv, wb.y, bv.y));
        float x2 = fmaf(dist, wa.z, fmaf(cosv, wb.z, bv.z));
        float x3 = fmaf(dist, wa.w, fmaf(cosv, wb.w, bv.w));
        float g0 = fmaxf(x0, 0.f);
        float g1 = fmaxf(x1, 0.f);
        float g2 = fmaxf(x2, 0.f);
        float g3 = fmaxf(x3, 0.f);
        if (fabsf(x0) < 6.f) g0 = 0.5f*x0*(1.f + erff(x0 * 0.70710678118654752f));
        if (fabsf(x1) < 6.f) g1 = 0.5f*x1*(1.f + erff(x1 * 0.70710678118654752f));
        if (fabsf(x2) < 6.f) g2 = 0.5f*x2*(1.f + erff(x2 * 0.70710678118654752f));
        if (fabsf(x3) < 6.f) g3 = 0.5f*x3*(1.f + erff(x3 * 0.70710678118654752f));
        z = fmaf(g0, w2v.x, z);
        z = fmaf(g1, w2v.y, z);
        z = fmaf(g2, w2v.z, z);
        z = fmaf(g3, w2v.w, z);
    }
    z += __shfl_xor_sync(0xffffffffu, z, 1);
    z += __shfl_xor_sync(0xffffffffu, z, 2);
    z += __shfl_xor_sync(0xffffffffu, z, 4);
    if (sub == 0) {
        if (!valid) { g_mu[slot] = 0.f; return; }
        float zz = z + b2[0];
        float sp = fmaxf(zz, 0.f) + log1pf(expf(-fabsf(zz)));
        g_mu[slot] = fminf(sp + 1e-5f, MU_MAXV);
    }
}

// ---------------------------------------------------------------------------
// deg -> isq
// ---------------------------------------------------------------------------
__global__ void deg_kernel()
{
    int i = blockIdx.x * blockDim.x + threadIdx.x;
    int b = blockIdx.y;
    if (i >= SS) return;
    float deg = 0.f;
#pragma unroll
    for (int d = 1; d <= RAD; d++) {
        if (i + d < SS) deg += g_mu[((size_t)b * RAD + (d - 1)) * SS + i];
        if (i >= d)     deg += g_mu[((size_t)b * RAD + (d - 1)) * SS + i - d];
    }
    g_isq[b * SS + i] = 1.f / sqrtf(fmaxf(deg, 1e-6f));
}

// ---------------------------------------------------------------------------
// Fused lap+update+smooth (R2 structure + ping-pong src/dst, race-free).
// Tile = 16 output rows; state rows [i0-9, i0+25) (34), tmp rows (18).
// ---------------------------------------------------------------------------
#define LT 16
#define LSROWS 34
#define LTROWS 18
#define LAPS_SMEM (((size_t)LSROWS * HH + (size_t)LTROWS * HH + \
                    LTROWS * 16 + LTROWS) * sizeof(float))

__global__ __launch_bounds__(256) void lapsmooth_kernel(
    const float* __restrict__ src, float* __restrict__ dst, float eta)
{
    extern __shared__ float sh[];
    float* st  = sh;                                 // LSROWS * HH
    float* tp  = st + (size_t)LSROWS * HH;           // LTROWS * HH
    float* cof = tp + (size_t)LTROWS * HH;           // LTROWS * 16
    float* csm = cof + LTROWS * 16;                  // LTROWS

    int tid = threadIdx.x;
    int b = blockIdx.y;
    int i0 = blockIdx.x * LT;

    // load state rows [i0-9, i0+25)
#pragma unroll
    for (int r = 0; r < LSROWS; r++) {
        int j = i0 - 9 + r;
        if (j >= 0 && j < SS)
            ((float4*)(st + (size_t)r * HH))[tid] =
                ((const float4*)(src + ((size_t)b * SS + j) * HH))[tid];
    }
    // coefficients for 18 tmp rows (clamped j)
    for (int idx = tid; idx < LTROWS * 16; idx += 256) {
        int jl = idx >> 4;
        int k = idx & 15;
        int j = i0 - 1 + jl;
        int je = min(max(j, 0), SS - 1);
        int d = (k >> 1) + 1;
        float c = 0.f;
        if (!(k & 1)) {                       // + direction
            int jn = je + d;
            if (jn < SS)
                c = g_mu[((size_t)b * RAD + (d - 1)) * SS + je] *
                    g_isq[b * SS + je] * g_isq[b * SS + jn];
        } else {                              // - direction
            int jn = je - d;
            if (jn >= 0)
                c = g_mu[((size_t)b * RAD + (d - 1)) * SS + jn] *
                    g_isq[b * SS + je] * g_isq[b * SS + jn];
        }
        cof[idx] = c;
    }
    __syncthreads();
    if (tid < LTROWS) {
        float s = 0.f;
#pragma unroll
        for (int k = 0; k < 16; k++) s += cof[tid * 16 + k];
        csm[tid] = s;
    }
    __syncthreads();

    // tmp rows
#pragma unroll
    for (int jl = 0; jl < LTROWS; jl++) {
        int j = i0 - 1 + jl;
        int je = min(max(j, 0), SS - 1);
        int jloc = je - i0 + 9;              // local state index
        float4 si = ((const float4*)(st + (size_t)jloc * HH))[tid];
        float cs = csm[jl];
        float4 acc;
        acc.x = cs * si.x; acc.y = cs * si.y; acc.z = cs * si.z; acc.w = cs * si.w;
#pragma unroll
        for (int k = 0; k < 16; k++) {
            float c = cof[jl * 16 + k];
            if (c != 0.f) {
                int d = (k >> 1) + 1;
                int off = (k & 1) ? -d : d;
                float4 sj = ((const float4*)(st + (size_t)(jloc + off) * HH))[tid];
                acc.x = fmaf(-c, sj.x, acc.x);
                acc.y = fmaf(-c, sj.y, acc.y);
                acc.z = fmaf(-c, sj.z, acc.z);
                acc.w = fmaf(-c, sj.w, acc.w);
            }
        }
        float4 qv = ((const float4*)(g_q + ((size_t)b * SS + je) * HH))[tid];
        float4 tv;
        tv.x = si.x - eta * (acc.x - qv.x);
        tv.y = si.y - eta * (acc.y - qv.y);
        tv.z = si.z - eta * (acc.z - qv.z);
        tv.w = si.w - eta * (acc.w - qv.w);
        ((float4*)(tp + (size_t)jl * HH))[tid] = tv;
    }
    __syncthreads();

    // smooth + writeback
#pragma unroll
    for (int il = 0; il < LT; il++) {
        int i = i0 + il;
        if (i >= SS) break;
        int jl = il + 1;
        float4 s = ((const float4*)(tp + (size_t)jl * HH))[tid];
        float4 l = ((const float4*)(tp + (size_t)(jl - 1) * HH))[tid];
        float4 r = ((const float4*)(tp + (size_t)(jl + 1) * HH))[tid];
        float4 o;
        o.x = s.x - LAMv * (2.f * s.x - l.x - r.x);
        o.y = s.y - LAMv * (2.f * s.y - l.y - r.y);
        o.z = s.z - LAMv * (2.f * s.z - l.z - r.z);
        o.w = s.w - LAMv * (2.f * s.w - l.w - r.w);
        ((float4*)(dst + ((size_t)b * SS + i) * HH))[tid] = o;
    }
}

// ---------------------------------------------------------------------------
// energy[b] = 0.5 * sum_e mu_e * (nsq_i + nsq_j - 2 dot_e)
// ---------------------------------------------------------------------------
__global__ __launch_bounds__(256) void energy_kernel(float* __restrict__ out)
{
    int b = blockIdx.x;
    int tid = threadIdx.x;
    float partial = 0.f;
    for (int e = tid; e < RAD * SS; e += 256) {
        int d = e >> 11;
        int i = e & 2047;
        if (i + d + 1 < SS) {
            size_t slot = ((size_t)b * RAD + d) * SS + i;
            float mu = g_mu[slot];
            float dsq = g_nsq[b * SS + i] + g_nsq[b * SS + i + d + 1]
                      - 2.f * g_dots[slot];
            partial += mu * dsq;
        }
    }
#pragma unroll
    for (int o = 16; o > 0; o >>= 1)
        partial += __shfl_xor_sync(0xffffffffu, partial, o);
    __shared__ float red[8];
    int wid = tid >> 5, lane = tid & 31;
    if (lane == 0) red[wid] = partial;
    __syncthreads();
    if (tid == 0) {
        float s = 0.f;
#pragma unroll
        for (int w = 0; w < 8; w++) s += red[w];
        out[(size_t)BSH + b] = 0.5f * s;
    }
}

// ---------------------------------------------------------------------------
// out = layernorm(final + hidden) * gamma + beta
// ---------------------------------------------------------------------------
__global__ __launch_bounds__(256) void ln_kernel(
    const float* __restrict__ fin,
    const float* __restrict__ hidden,
    const float* __restrict__ gamma, const float* __restrict__ beta,
    float* __restrict__ out)
{
    int i = blockIdx.x, b = blockIdx.y;
    int tid = threadIdx.x;
    size_t base = ((size_t)b * SS + i) * HH + tid * 4;
    float4 s = *(const float4*)&fin[base];
    float4 h = *(const float4*)&hidden[base];
    float4 x;
    x.x = s.x + h.x; x.y = s.y + h.y; x.z = s.z + h.z; x.w = s.w + h.w;
    float sum = x.x + x.y + x.z + x.w;
    float sq  = x.x*x.x + x.y*x.y + x.z*x.z + x.w*x.w;
#pragma unroll
    for (int o = 16; o > 0; o >>= 1) {
        sum += __shfl_xor_sync(0xffffffffu, sum, o);
        sq  += __shfl_xor_sync(0xffffffffu, sq,  o);
    }
    __shared__ float rs[8], rq[8];
    int wid = tid >> 5, lane = tid & 31;
    if (lane == 0) { rs[wid] = sum; rq[wid] = sq; }
    __syncthreads();
    __shared__ float s_mean, s_rstd;
    if (tid == 0) {
        float ts = 0.f, tq = 0.f;
#pragma unroll
        for (int w = 0; w < 8; w++) { ts += rs[w]; tq += rq[w]; }
        float mean = ts / HH;
        float var = tq / HH - mean * mean;
        s_mean = mean;
        s_rstd = rsqrtf(var + 1e-5f);
    }
    __syncthreads();
    float mean = s_mean, rstd = s_rstd;
    int hbase = tid * 4;
    float4 o;
    o.x = (x.x - mean) * rstd * gamma[hbase+0] + beta[hbase+0];
    o.y = (x.y - mean) * rstd * gamma[hbase+1] + beta[hbase+1];
    o.z = (x.z - mean) * rstd * gamma[hbase+2] + beta[hbase+2];
    o.w = (x.w - mean) * rstd * gamma[hbase+3] + beta[hbase+3];
    *(float4*)&out[base] = o;
}

// ---------------------------------------------------------------------------
extern "C" void kernel_launch(void* const* d_in, const int* in_sizes, int n_in,
                              void* d_out, int out_size)
{
    const float* hidden = (const float*)d_in[0];
    const float* Wq = (const float*)d_in[3];
    const float* bq = (const float*)d_in[4];
    const float* W1 = (const float*)d_in[5];
    const float* b1 = (const float*)d_in[6];
    const float* W2 = (const float*)d_in[7];
    const float* b2 = (const float*)d_in[8];
    const float* gamma = (const float*)d_in[9];
    const float* beta  = (const float*)d_in[10];
    float* out = (float*)d_out;

    float *pA = nullptr, *pB = nullptr;
    cudaGetSymbolAddress((void**)&pA, g_stateA);
    cudaGetSymbolAddress((void**)&pB, g_stateB);

    cudaFuncSetAttribute(dots_tiled_kernel,
                         cudaFuncAttributeMaxDynamicSharedMemorySize, DOTS_SMEM);
    cudaFuncSetAttribute(lapsmooth_kernel,
                         cudaFuncAttributeMaxDynamicSharedMemorySize, LAPS_SMEM);

    gemm_tf32_kernel<<<dim3(HH / TN, (BB * SS) / TM), 256>>>(hidden, Wq, bq);

    // ping-pong: hidden -> A -> B -> A -> B
    const float* srcs[KSTEPS + 1] = { hidden, pA, pB, pA, pB };
    float*       dsts[KSTEPS]     = { pA, pB, pA, pB };

    const int dots_grid = (SS + DT - 1) / DT;   // 86
    float eta = 0.1f;
    for (int step = 0; step < KSTEPS; step++) {
        dots_tiled_kernel<<<dim3(dots_grid, BB), 256, DOTS_SMEM>>>(srcs[step]);
        mu_kernel3<<<(BB * RAD * SS) / 32, 256>>>(W1, b1, W2, b2);
        deg_kernel<<<dim3(SS / 256, BB), 256>>>();
        lapsmooth_kernel<<<dim3(SS / LT, BB), 256, LAPS_SMEM>>>(srcs[step], dsts[step], eta);
        eta *= 0.9f;
    }
    dots_tiled_kernel<<<dim3(dots_grid, BB), 256, DOTS_SMEM>>>(srcs[KSTEPS]);
    energy_kernel<<<BB, 256>>>(out);
    ln_kernel<<<dim3(SS, BB), 256>>>(srcs[KSTEPS], hidden, gamma, beta, out);
}

// round 6
// speedup vs baseline: 1.0296x; 1.0296x over previous
#include <cuda_runtime.h>
#include <math.h>
#include <stdint.h>

#define BB 4
#define SS 2048
#define HH 1024
#define INNERD 512
#define RAD 8
#define KSTEPS 4
#define LAMv 0.1f
#define MU_MAXV 10.0f

#define BSH (BB*SS*HH)

// Scratch (no cudaMalloc allowed). Ping-pong state buffers.
__device__ float g_q[BSH];
__device__ float g_stateA[BSH];
__device__ float g_stateB[BSH];
__device__ float g_nsq[BB*SS];
__device__ float g_dots[BB*RAD*SS];
__device__ float g_mu[BB*RAD*SS];

__device__ __forceinline__ float to_tf32(float x) {
    float r;
    asm("cvt.rna.tf32.f32 %0, %1;" : "=f"(r) : "f"(x));
    return r;
}

// ---------------------------------------------------------------------------
// GEMM (TF32 mma.sync): q = hidden @ Wq + bq.  M=8192, N=K=1024.
// Block 128x128, 8 warps, warp 32x64, K-step 32.  (R2 version, measured good.)
// ---------------------------------------------------------------------------
#define TM 128
#define TN 128
#define TK 32

__global__ __launch_bounds__(256) void gemm_tf32_kernel(
    const float* __restrict__ A,
    const float* __restrict__ W,
    const float* __restrict__ bias)
{
    const int N = HH, K = HH;
    __shared__ float As[TK][TM + 4];   // k-major
    __shared__ float Bs[TK][TN + 4];

    int tid = threadIdx.x;
    int m0 = blockIdx.y * TM;
    int n0 = blockIdx.x * TN;
    int wid = tid >> 5, lane = tid & 31;
    int wm = (wid & 3) * 32;
    int wn = (wid >> 2) * 64;
    int gid = lane >> 2, tig = lane & 3;

    float acc[2][8][4];
#pragma unroll
    for (int mt = 0; mt < 2; mt++)
#pragma unroll
        for (int nt = 0; nt < 8; nt++)
#pragma unroll
            for (int c = 0; c < 4; c++) acc[mt][nt][c] = 0.f;

    int a_row = tid >> 3;            // 0..31
    int a_k4  = (tid & 7) * 4;       // 0..28
    int b_k   = tid >> 5;            // 0..7
    int b_n4  = (tid & 31) * 4;      // 0..124

    for (int k0 = 0; k0 < K; k0 += TK) {
        __syncthreads();
#pragma unroll
        for (int r = 0; r < 4; r++) {
            int m = a_row + r * 32;
            float4 v = *(const float4*)&A[(size_t)(m0 + m) * K + k0 + a_k4];
            As[a_k4 + 0][m] = to_tf32(v.x);
            As[a_k4 + 1][m] = to_tf32(v.y);
            As[a_k4 + 2][m] = to_tf32(v.z);
            As[a_k4 + 3][m] = to_tf32(v.w);
        }
#pragma unroll
        for (int r = 0; r < 4; r++) {
            int k = b_k + r * 8;
            float4 v = *(const float4*)&W[(size_t)(k0 + k) * N + n0 + b_n4];
            Bs[k][b_n4 + 0] = to_tf32(v.x);
            Bs[k][b_n4 + 1] = to_tf32(v.y);
            Bs[k][b_n4 + 2] = to_tf32(v.z);
            Bs[k][b_n4 + 3] = to_tf32(v.w);
        }
        __syncthreads();

#pragma unroll
        for (int ks = 0; ks < 4; ks++) {
            int kb = ks * 8;
            uint32_t af[2][4];
#pragma unroll
            for (int mt = 0; mt < 2; mt++) {
                int rm = wm + mt * 16 + gid;
                af[mt][0] = __float_as_uint(As[kb + tig][rm]);
                af[mt][1] = __float_as_uint(As[kb + tig][rm + 8]);
                af[mt][2] = __float_as_uint(As[kb + tig + 4][rm]);
                af[mt][3] = __float_as_uint(As[kb + tig + 4][rm + 8]);
            }
            uint32_t bf[8][2];
#pragma unroll
            for (int nt = 0; nt < 8; nt++) {
                int cn = wn + nt * 8 + gid;
                bf[nt][0] = __float_as_uint(Bs[kb + tig][cn]);
                bf[nt][1] = __float_as_uint(Bs[kb + tig + 4][cn]);
            }
#pragma unroll
            for (int mt = 0; mt < 2; mt++)
#pragma unroll
                for (int nt = 0; nt < 8; nt++) {
                    asm volatile(
                        "mma.sync.aligned.m16n8k8.row.col.f32.tf32.tf32.f32 "
                        "{%0,%1,%2,%3}, {%4,%5,%6,%7}, {%8,%9}, {%0,%1,%2,%3};"
                        : "+f"(acc[mt][nt][0]), "+f"(acc[mt][nt][1]),
                          "+f"(acc[mt][nt][2]), "+f"(acc[mt][nt][3])
                        : "r"(af[mt][0]), "r"(af[mt][1]),
                          "r"(af[mt][2]), "r"(af[mt][3]),
                          "r"(bf[nt][0]), "r"(bf[nt][1]));
                }
        }
    }

#pragma unroll
    for (int mt = 0; mt < 2; mt++) {
        int row0 = m0 + wm + mt * 16 + gid;
#pragma unroll
        for (int nt = 0; nt < 8; nt++) {
            int col = n0 + wn + nt * 8 + 2 * tig;
            float bx = bias[col], by = bias[col + 1];
            float2 v0 = make_float2(acc[mt][nt][0] + bx, acc[mt][nt][1] + by);
            float2 v1 = make_float2(acc[mt][nt][2] + bx, acc[mt][nt][3] + by);
            *(float2*)&g_q[(size_t)row0 * N + col] = v0;
            *(float2*)&g_q[(size_t)(row0 + 8) * N + col] = v1;
        }
    }
}

// ---------------------------------------------------------------------------
// Tiled dots: block = 24 nodes (+8 halo rows). nsq + dots[d=1..8].
// ---------------------------------------------------------------------------
#define DT 24
#define DROWS 32
#define DOTS_SMEM (DROWS * HH * sizeof(float))

__global__ __launch_bounds__(256) void dots_tiled_kernel(const float* __restrict__ src)
{
    extern __shared__ float sh[];  // DROWS * HH
    int tid = threadIdx.x;
    int b = blockIdx.y;
    int i0 = blockIdx.x * DT;

#pragma unroll
    for (int r = 0; r < DROWS; r++) {
        int i = i0 + r;
        if (i < SS)
            ((float4*)(sh + (size_t)r * HH))[tid] =
                ((const float4*)(src + ((size_t)b * SS + i) * HH))[tid];
    }
    __syncthreads();

    int w = tid >> 5, lane = tid & 31;
#pragma unroll
    for (int nn = 0; nn < 3; nn++) {
        int ln = w * 3 + nn;          // 0..23
        int i = i0 + ln;
        if (i >= SS) continue;
        const float4* arow = (const float4*)(sh + (size_t)ln * HH);
        float4 a[8];
#pragma unroll
        for (int r = 0; r < 8; r++) a[r] = arow[lane + 32 * r];

#pragma unroll
        for (int d = 0; d <= RAD; d++) {
            if (d > 0 && i + d >= SS) break;
            float sum = 0.f;
            if (d == 0) {
#pragma unroll
                for (int r = 0; r < 8; r++)
                    sum += a[r].x*a[r].x + a[r].y*a[r].y + a[r].z*a[r].z + a[r].w*a[r].w;
            } else {
                const float4* crow = (const float4*)(sh + (size_t)(ln + d) * HH);
#pragma unroll
                for (int r = 0; r < 8; r++) {
                    float4 c = crow[lane + 32 * r];
                    sum += a[r].x*c.x + a[r].y*c.y + a[r].z*c.z + a[r].w*c.w;
                }
            }
#pragma unroll
            for (int o = 16; o > 0; o >>= 1)
                sum += __shfl_xor_sync(0xffffffffu, sum, o);
            if (lane == 0) {
                if (d == 0) g_nsq[b * SS + i] = sum;
                else g_dots[((size_t)b * RAD + (d - 1)) * SS + i] = sum;
            }
        }
    }
}

// ---------------------------------------------------------------------------
// mu: 8 threads per edge (64 channels each), weights in smem, GELU fast-path.
// ---------------------------------------------------------------------------
__global__ __launch_bounds__(256) void mu_kernel3(
    const float* __restrict__ W1, const float* __restrict__ b1,
    const float* __restrict__ W2, const float* __restrict__ b2)
{
    __shared__ float w1a[INNERD], w1b[INNERD], bb1[INNERD], w2s[INNERD];
    int tid = threadIdx.x;
#pragma unroll
    for (int r = 0; r < 2; r++) {
        int k = tid + 256 * r;
        w1a[k] = W1[k];
        w1b[k] = W1[INNERD + k];
        bb1[k] = b1[k];
        w2s[k] = W2[k];
    }
    __syncthreads();

    int e = blockIdx.x * 32 + (tid >> 3);     // edge id
    int sub = tid & 7;
    int b = e >> 14;
    int r = e & 16383;
    int d = (r >> 11) + 1;
    int i = r & 2047;
    size_t slot = ((size_t)b * RAD + (d - 1)) * SS + i;
    bool valid = (i + d < SS);

    int j = valid ? (i + d) : i;
    float nsqi = g_nsq[b * SS + i];
    float nsqj = g_nsq[b * SS + j];
    float dot  = valid ? g_dots[slot] : 0.f;
    float dist = sqrtf(fmaxf(nsqi + nsqj - 2.f * dot, 0.f));
    float ni = fmaxf(sqrtf(nsqi), 1e-6f);
    float nj = fmaxf(sqrtf(nsqj), 1e-6f);
    float cosv = dot / (ni * nj);

    float z = 0.f;
    int kbase = sub * 64;
#pragma unroll 4
    for (int k = kbase; k < kbase + 64; k += 4) {
        float4 wa = *(const float4*)&w1a[k];
        float4 wb = *(const float4*)&w1b[k];
        float4 bv = *(const float4*)&bb1[k];
        float4 w2v = *(const float4*)&w2s[k];
        float x0 = fmaf(dist, wa.x, fmaf(cosv, wb.x, bv.x));
        float x1 = fmaf(dist, wa.y, fmaf(cosv, wb.y, bv.y));
        float x2 = fmaf(dist, wa.z, fmaf(cosv, wb.z, bv.z));
        float x3 = fmaf(dist, wa.w, fmaf(cosv, wb.w, bv.w));
        float g0 = fmaxf(x0, 0.f);
        float g1 = fmaxf(x1, 0.f);
        float g2 = fmaxf(x2, 0.f);
        float g3 = fmaxf(x3, 0.f);
        if (fabsf(x0) < 6.f) g0 = 0.5f*x0*(1.f + erff(x0 * 0.70710678118654752f));
        if (fabsf(x1) < 6.f) g1 = 0.5f*x1*(1.f + erff(x1 * 0.70710678118654752f));
        if (fabsf(x2) < 6.f) g2 = 0.5f*x2*(1.f + erff(x2 * 0.70710678118654752f));
        if (fabsf(x3) < 6.f) g3 = 0.5f*x3*(1.f + erff(x3 * 0.70710678118654752f));
        z = fmaf(g0, w2v.x, z);
        z = fmaf(g1, w2v.y, z);
        z = fmaf(g2, w2v.z, z);
        z = fmaf(g3, w2v.w, z);
    }
    z += __shfl_xor_sync(0xffffffffu, z, 1);
    z += __shfl_xor_sync(0xffffffffu, z, 2);
    z += __shfl_xor_sync(0xffffffffu, z, 4);
    if (sub == 0) {
        if (!valid) { g_mu[slot] = 0.f; return; }
        float zz = z + b2[0];
        float sp = fmaxf(zz, 0.f) + log1pf(expf(-fabsf(zz)));
        g_mu[slot] = fminf(sp + 1e-5f, MU_MAXV);
    }
}

// ---------------------------------------------------------------------------
// Fused deg+lap+update+smooth. src -> dst (ping-pong, race-free).
// Tile = 16 output rows; state rows [i0-9, i0+25) (34), tmp rows (18).
// isq computed in-block for the 34 nodes [i0-9, i0+25) (deg kernel fused).
// ---------------------------------------------------------------------------
#define LT 16
#define LSROWS 34
#define LTROWS 18
#define LAPS_SMEM (((size_t)LSROWS * HH + (size_t)LTROWS * HH + \
                    LTROWS * 16 + LTROWS + LSROWS) * sizeof(float))

__global__ __launch_bounds__(256) void lapsmooth_kernel(
    const float* __restrict__ src, float* __restrict__ dst, float eta)
{
    extern __shared__ float sh[];
    float* st   = sh;                                 // LSROWS * HH
    float* tp   = st + (size_t)LSROWS * HH;           // LTROWS * HH
    float* cof  = tp + (size_t)LTROWS * HH;           // LTROWS * 16
    float* csm  = cof + LTROWS * 16;                  // LTROWS
    float* isqs = csm + LTROWS;                       // LSROWS (nodes i0-9..i0+24)

    int tid = threadIdx.x;
    int b = blockIdx.y;
    int i0 = blockIdx.x * LT;

    // load state rows [i0-9, i0+25)
#pragma unroll
    for (int r = 0; r < LSROWS; r++) {
        int j = i0 - 9 + r;
        if (j >= 0 && j < SS)
            ((float4*)(st + (size_t)r * HH))[tid] =
                ((const float4*)(src + ((size_t)b * SS + j) * HH))[tid];
    }
    // fused deg: isq for nodes [i0-9, i0+25)
    if (tid < LSROWS) {
        int n = i0 - 9 + tid;
        float isq = 0.f;
        if (n >= 0 && n < SS) {
            float deg = 0.f;
#pragma unroll
            for (int d = 1; d <= RAD; d++) {
                if (n + d < SS) deg += g_mu[((size_t)b * RAD + (d - 1)) * SS + n];
                if (n >= d)     deg += g_mu[((size_t)b * RAD + (d - 1)) * SS + n - d];
            }
            isq = rsqrtf(fmaxf(deg, 1e-6f));
        }
        isqs[tid] = isq;
    }
    __syncthreads();

    // coefficients for 18 tmp rows (clamped j)
    for (int idx = tid; idx < LTROWS * 16; idx += 256) {
        int jl = idx >> 4;
        int k = idx & 15;
        int j = i0 - 1 + jl;
        int je = min(max(j, 0), SS - 1);
        int d = (k >> 1) + 1;
        float c = 0.f;
        if (!(k & 1)) {                       // + direction
            int jn = je + d;
            if (jn < SS)
                c = g_mu[((size_t)b * RAD + (d - 1)) * SS + je] *
                    isqs[je - (i0 - 9)] * isqs[jn - (i0 - 9)];
        } else {                              // - direction
            int jn = je - d;
            if (jn >= 0)
                c = g_mu[((size_t)b * RAD + (d - 1)) * SS + jn] *
                    isqs[je - (i0 - 9)] * isqs[jn - (i0 - 9)];
        }
        cof[idx] = c;
    }
    __syncthreads();
    if (tid < LTROWS) {
        float s = 0.f;
#pragma unroll
        for (int k = 0; k < 16; k++) s += cof[tid * 16 + k];
        csm[tid] = s;
    }
    __syncthreads();

    // tmp rows
#pragma unroll
    for (int jl = 0; jl < LTROWS; jl++) {
        int j = i0 - 1 + jl;
        int je = min(max(j, 0), SS - 1);
        int jloc = je - i0 + 9;              // local state index
        float4 si = ((const float4*)(st + (size_t)jloc * HH))[tid];
        float cs = csm[jl];
        float4 acc;
        acc.x = cs * si.x; acc.y = cs * si.y; acc.z = cs * si.z; acc.w = cs * si.w;
#pragma unroll
        for (int k = 0; k < 16; k++) {
            float c = cof[jl * 16 + k];
            if (c != 0.f) {
                int d = (k >> 1) + 1;
                int off = (k & 1) ? -d : d;
                float4 sj = ((const float4*)(st + (size_t)(jloc + off) * HH))[tid];
                acc.x = fmaf(-c, sj.x, acc.x);
                acc.y = fmaf(-c, sj.y, acc.y);
                acc.z = fmaf(-c, sj.z, acc.z);
                acc.w = fmaf(-c, sj.w, acc.w);
            }
        }
        float4 qv = ((const float4*)(g_q + ((size_t)b * SS + je) * HH))[tid];
        float4 tv;
        tv.x = si.x - eta * (acc.x - qv.x);
        tv.y = si.y - eta * (acc.y - qv.y);
        tv.z = si.z - eta * (acc.z - qv.z);
        tv.w = si.w - eta * (acc.w - qv.w);
        ((float4*)(tp + (size_t)jl * HH))[tid] = tv;
    }
    __syncthreads();

    // smooth + writeback
#pragma unroll
    for (int il = 0; il < LT; il++) {
        int i = i0 + il;
        if (i >= SS) break;
        int jl = il + 1;
        float4 s = ((const float4*)(tp + (size_t)jl * HH))[tid];
        float4 l = ((const float4*)(tp + (size_t)(jl - 1) * HH))[tid];
        float4 r = ((const float4*)(tp + (size_t)(jl + 1) * HH))[tid];
        float4 o;
        o.x = s.x - LAMv * (2.f * s.x - l.x - r.x);
        o.y = s.y - LAMv * (2.f * s.y - l.y - r.y);
        o.z = s.z - LAMv * (2.f * s.z - l.z - r.z);
        o.w = s.w - LAMv * (2.f * s.w - l.w - r.w);
        ((float4*)(dst + ((size_t)b * SS + i) * HH))[tid] = o;
    }
}

// ---------------------------------------------------------------------------
// Zero energy slots (out[BSH .. BSH+BB))
// ---------------------------------------------------------------------------
__global__ void zero_energy_kernel(float* __restrict__ out)
{
    if (threadIdx.x < BB) out[(size_t)BSH + threadIdx.x] = 0.f;
}

// ---------------------------------------------------------------------------
// Fused final energy: per tile, energy += 0.5 * sum mu_e * ||s_i - s_j||^2.
// Same tiling as dots. atomicAdd per block.
// ---------------------------------------------------------------------------
__global__ __launch_bounds__(256) void energy_tiled_kernel(
    const float* __restrict__ src, float* __restrict__ out)
{
    extern __shared__ float sh[];  // DROWS * HH
    int tid = threadIdx.x;
    int b = blockIdx.y;
    int i0 = blockIdx.x * DT;

#pragma unroll
    for (int r = 0; r < DROWS; r++) {
        int i = i0 + r;
        if (i < SS)
            ((float4*)(sh + (size_t)r * HH))[tid] =
                ((const float4*)(src + ((size_t)b * SS + i) * HH))[tid];
    }
    __syncthreads();

    int w = tid >> 5, lane = tid & 31;
    float wpart = 0.f;
#pragma unroll
    for (int nn = 0; nn < 3; nn++) {
        int ln = w * 3 + nn;
        int i = i0 + ln;
        if (i >= SS) continue;
        const float4* arow = (const float4*)(sh + (size_t)ln * HH);
        float4 a[8];
#pragma unroll
        for (int r = 0; r < 8; r++) a[r] = arow[lane + 32 * r];
#pragma unroll
        for (int d = 1; d <= RAD; d++) {
            if (i + d >= SS) break;
            const float4* crow = (const float4*)(sh + (size_t)(ln + d) * HH);
            float sum = 0.f;
#pragma unroll
            for (int r = 0; r < 8; r++) {
                float4 c = crow[lane + 32 * r];
                float dx = a[r].x - c.x, dy = a[r].y - c.y;
                float dz = a[r].z - c.z, dw = a[r].w - c.w;
                sum += dx*dx + dy*dy + dz*dz + dw*dw;
            }
#pragma unroll
            for (int o = 16; o > 0; o >>= 1)
                sum += __shfl_xor_sync(0xffffffffu, sum, o);
            if (lane == 0)
                wpart += g_mu[((size_t)b * RAD + (d - 1)) * SS + i] * sum;
        }
    }
    __shared__ float red[8];
    if (lane == 0) red[w] = wpart;
    __syncthreads();
    if (tid == 0) {
        float s = 0.f;
#pragma unroll
        for (int ww = 0; ww < 8; ww++) s += red[ww];
        atomicAdd(&out[(size_t)BSH + b], 0.5f * s);
    }
}

// ---------------------------------------------------------------------------
// out = layernorm(final + hidden) * gamma + beta
// ---------------------------------------------------------------------------
__global__ __launch_bounds__(256) void ln_kernel(
    const float* __restrict__ fin,
    const float* __restrict__ hidden,
    const float* __restrict__ gamma, const float* __restrict__ beta,
    float* __restrict__ out)
{
    int i = blockIdx.x, b = blockIdx.y;
    int tid = threadIdx.x;
    size_t base = ((size_t)b * SS + i) * HH + tid * 4;
    float4 s = *(const float4*)&fin[base];
    float4 h = *(const float4*)&hidden[base];
    float4 x;
    x.x = s.x + h.x; x.y = s.y + h.y; x.z = s.z + h.z; x.w = s.w + h.w;
    float sum = x.x + x.y + x.z + x.w;
    float sq  = x.x*x.x + x.y*x.y + x.z*x.z + x.w*x.w;
#pragma unroll
    for (int o = 16; o > 0; o >>= 1) {
        sum += __shfl_xor_sync(0xffffffffu, sum, o);
        sq  += __shfl_xor_sync(0xffffffffu, sq,  o);
    }
    __shared__ float rs[8], rq[8];
    int wid = tid >> 5, lane = tid & 31;
    if (lane == 0) { rs[wid] = sum; rq[wid] = sq; }
    __syncthreads();
    __shared__ float s_mean, s_rstd;
    if (tid == 0) {
        float ts = 0.f, tq = 0.f;
#pragma unroll
        for (int w = 0; w < 8; w++) { ts += rs[w]; tq += rq[w]; }
        float mean = ts / HH;
        float var = tq / HH - mean * mean;
        s_mean = mean;
        s_rstd = rsqrtf(var + 1e-5f);
    }
    __syncthreads();
    float mean = s_mean, rstd = s_rstd;
    int hbase = tid * 4;
    float4 o;
    o.x = (x.x - mean) * rstd * gamma[hbase+0] + beta[hbase+0];
    o.y = (x.y - mean) * rstd * gamma[hbase+1] + beta[hbase+1];
    o.z = (x.z - mean) * rstd * gamma[hbase+2] + beta[hbase+2];
    o.w = (x.w - mean) * rstd * gamma[hbase+3] + beta[hbase+3];
    *(float4*)&out[base] = o;
}

// ---------------------------------------------------------------------------
extern "C" void kernel_launch(void* const* d_in, const int* in_sizes, int n_in,
                              void* d_out, int out_size)
{
    const float* hidden = (const float*)d_in[0];
    const float* Wq = (const float*)d_in[3];
    const float* bq = (const float*)d_in[4];
    const float* W1 = (const float*)d_in[5];
    const float* b1 = (const float*)d_in[6];
    const float* W2 = (const float*)d_in[7];
    const float* b2 = (const float*)d_in[8];
    const float* gamma = (const float*)d_in[9];
    const float* beta  = (const float*)d_in[10];
    float* out = (float*)d_out;

    float *pA = nullptr, *pB = nullptr;
    cudaGetSymbolAddress((void**)&pA, g_stateA);
    cudaGetSymbolAddress((void**)&pB, g_stateB);

    cudaFuncSetAttribute(dots_tiled_kernel,
                         cudaFuncAttributeMaxDynamicSharedMemorySize, DOTS_SMEM);
    cudaFuncSetAttribute(energy_tiled_kernel,
                         cudaFuncAttributeMaxDynamicSharedMemorySize, DOTS_SMEM);
    cudaFuncSetAttribute(lapsmooth_kernel,
                         cudaFuncAttributeMaxDynamicSharedMemorySize, LAPS_SMEM);

    gemm_tf32_kernel<<<dim3(HH / TN, (BB * SS) / TM), 256>>>(hidden, Wq, bq);
    zero_energy_kernel<<<1, 32>>>(out);

    // ping-pong: hidden -> A -> B -> A -> B
    const float* srcs[KSTEPS + 1] = { hidden, pA, pB, pA, pB };
    float*       dsts[KSTEPS]     = { pA, pB, pA, pB };

    const int dots_grid = (SS + DT - 1) / DT;   // 86
    float eta = 0.1f;
    for (int step = 0; step < KSTEPS; step++) {
        dots_tiled_kernel<<<dim3(dots_grid, BB), 256, DOTS_SMEM>>>(srcs[step]);
        mu_kernel3<<<(BB * RAD * SS) / 32, 256>>>(W1, b1, W2, b2);
        lapsmooth_kernel<<<dim3(SS / LT, BB), 256, LAPS_SMEM>>>(srcs[step], dsts[step], eta);
        eta *= 0.9f;
    }
    energy_tiled_kernel<<<dim3(dots_grid, BB), 256, DOTS_SMEM>>>(srcs[KSTEPS], out);
    ln_kernel<<<dim3(SS, BB), 256>>>(srcs[KSTEPS], hidden, gamma, beta, out);
}

// round 7
// speedup vs baseline: 1.4467x; 1.4050x over previous
#include <cuda_runtime.h>
#include <math.h>
#include <stdint.h>

#define BB 4
#define SS 2048
#define HH 1024
#define INNERD 512
#define RAD 8
#define KSTEPS 4
#define LAMv 0.1f
#define MU_MAXV 10.0f

#define BSH (BB*SS*HH)

// Scratch (no cudaMalloc allowed). Ping-pong state buffers.
__device__ float g_q[BSH];
__device__ float g_stateA[BSH];
__device__ float g_stateB[BSH];
__device__ float g_nsq[BB*SS];
__device__ float g_dots[BB*RAD*SS];
__device__ float g_mu[BB*RAD*SS];

__device__ __forceinline__ float to_tf32(float x) {
    float r;
    asm("cvt.rna.tf32.f32 %0, %1;" : "=f"(r) : "f"(x));
    return r;
}

// ---------------------------------------------------------------------------
// GEMM (TF32 mma.sync): q = hidden @ Wq + bq.  M=8192, N=K=1024.
// Block 128x128, 8 warps, warp 32x64, K-step 32.
// ---------------------------------------------------------------------------
#define TM 128
#define TN 128
#define TK 32

__global__ __launch_bounds__(256) void gemm_tf32_kernel(
    const float* __restrict__ A,
    const float* __restrict__ W,
    const float* __restrict__ bias)
{
    const int N = HH, K = HH;
    __shared__ float As[TK][TM + 4];   // k-major
    __shared__ float Bs[TK][TN + 4];

    int tid = threadIdx.x;
    int m0 = blockIdx.y * TM;
    int n0 = blockIdx.x * TN;
    int wid = tid >> 5, lane = tid & 31;
    int wm = (wid & 3) * 32;
    int wn = (wid >> 2) * 64;
    int gid = lane >> 2, tig = lane & 3;

    float acc[2][8][4];
#pragma unroll
    for (int mt = 0; mt < 2; mt++)
#pragma unroll
        for (int nt = 0; nt < 8; nt++)
#pragma unroll
            for (int c = 0; c < 4; c++) acc[mt][nt][c] = 0.f;

    int a_row = tid >> 3;            // 0..31
    int a_k4  = (tid & 7) * 4;       // 0..28
    int b_k   = tid >> 5;            // 0..7
    int b_n4  = (tid & 31) * 4;      // 0..124

    for (int k0 = 0; k0 < K; k0 += TK) {
        __syncthreads();
#pragma unroll
        for (int r = 0; r < 4; r++) {
            int m = a_row + r * 32;
            float4 v = *(const float4*)&A[(size_t)(m0 + m) * K + k0 + a_k4];
            As[a_k4 + 0][m] = to_tf32(v.x);
            As[a_k4 + 1][m] = to_tf32(v.y);
            As[a_k4 + 2][m] = to_tf32(v.z);
            As[a_k4 + 3][m] = to_tf32(v.w);
        }
#pragma unroll
        for (int r = 0; r < 4; r++) {
            int k = b_k + r * 8;
            float4 v = *(const float4*)&W[(size_t)(k0 + k) * N + n0 + b_n4];
            Bs[k][b_n4 + 0] = to_tf32(v.x);
            Bs[k][b_n4 + 1] = to_tf32(v.y);
            Bs[k][b_n4 + 2] = to_tf32(v.z);
            Bs[k][b_n4 + 3] = to_tf32(v.w);
        }
        __syncthreads();

#pragma unroll
        for (int ks = 0; ks < 4; ks++) {
            int kb = ks * 8;
            uint32_t af[2][4];
#pragma unroll
            for (int mt = 0; mt < 2; mt++) {
                int rm = wm + mt * 16 + gid;
                af[mt][0] = __float_as_uint(As[kb + tig][rm]);
                af[mt][1] = __float_as_uint(As[kb + tig][rm + 8]);
                af[mt][2] = __float_as_uint(As[kb + tig + 4][rm]);
                af[mt][3] = __float_as_uint(As[kb + tig + 4][rm + 8]);
            }
            uint32_t bf[8][2];
#pragma unroll
            for (int nt = 0; nt < 8; nt++) {
                int cn = wn + nt * 8 + gid;
                bf[nt][0] = __float_as_uint(Bs[kb + tig][cn]);
                bf[nt][1] = __float_as_uint(Bs[kb + tig + 4][cn]);
            }
#pragma unroll
            for (int mt = 0; mt < 2; mt++)
#pragma unroll
                for (int nt = 0; nt < 8; nt++) {
                    asm volatile(
                        "mma.sync.aligned.m16n8k8.row.col.f32.tf32.tf32.f32 "
                        "{%0,%1,%2,%3}, {%4,%5,%6,%7}, {%8,%9}, {%0,%1,%2,%3};"
                        : "+f"(acc[mt][nt][0]), "+f"(acc[mt][nt][1]),
                          "+f"(acc[mt][nt][2]), "+f"(acc[mt][nt][3])
                        : "r"(af[mt][0]), "r"(af[mt][1]),
                          "r"(af[mt][2]), "r"(af[mt][3]),
                          "r"(bf[nt][0]), "r"(bf[nt][1]));
                }
        }
    }

#pragma unroll
    for (int mt = 0; mt < 2; mt++) {
        int row0 = m0 + wm + mt * 16 + gid;
#pragma unroll
        for (int nt = 0; nt < 8; nt++) {
            int col = n0 + wn + nt * 8 + 2 * tig;
            float bx = bias[col], by = bias[col + 1];
            float2 v0 = make_float2(acc[mt][nt][0] + bx, acc[mt][nt][1] + by);
            float2 v1 = make_float2(acc[mt][nt][2] + bx, acc[mt][nt][3] + by);
            *(float2*)&g_q[(size_t)row0 * N + col] = v0;
            *(float2*)&g_q[(size_t)(row0 + 8) * N + col] = v1;
        }
    }
}

// ---------------------------------------------------------------------------
// Tiled dots: block = 24 nodes (+8 halo rows). nsq + dots[d=1..8].
// ---------------------------------------------------------------------------
#define DT 24
#define DROWS 32
#define DOTS_SMEM (DROWS * HH * sizeof(float))

__global__ __launch_bounds__(256) void dots_tiled_kernel(const float* __restrict__ src)
{
    extern __shared__ float sh[];  // DROWS * HH
    int tid = threadIdx.x;
    int b = blockIdx.y;
    int i0 = blockIdx.x * DT;

#pragma unroll
    for (int r = 0; r < DROWS; r++) {
        int i = i0 + r;
        if (i < SS)
            ((float4*)(sh + (size_t)r * HH))[tid] =
                ((const float4*)(src + ((size_t)b * SS + i) * HH))[tid];
    }
    __syncthreads();

    int w = tid >> 5, lane = tid & 31;
#pragma unroll
    for (int nn = 0; nn < 3; nn++) {
        int ln = w * 3 + nn;          // 0..23
        int i = i0 + ln;
        if (i >= SS) continue;
        const float4* arow = (const float4*)(sh + (size_t)ln * HH);
        float4 a[8];
#pragma unroll
        for (int r = 0; r < 8; r++) a[r] = arow[lane + 32 * r];

#pragma unroll
        for (int d = 0; d <= RAD; d++) {
            if (d > 0 && i + d >= SS) break;
            float sum = 0.f;
            if (d == 0) {
#pragma unroll
                for (int r = 0; r < 8; r++)
                    sum += a[r].x*a[r].x + a[r].y*a[r].y + a[r].z*a[r].z + a[r].w*a[r].w;
            } else {
                const float4* crow = (const float4*)(sh + (size_t)(ln + d) * HH);
#pragma unroll
                for (int r = 0; r < 8; r++) {
                    float4 c = crow[lane + 32 * r];
                    sum += a[r].x*c.x + a[r].y*c.y + a[r].z*c.z + a[r].w*c.w;
                }
            }
#pragma unroll
            for (int o = 16; o > 0; o >>= 1)
                sum += __shfl_xor_sync(0xffffffffu, sum, o);
            if (lane == 0) {
                if (d == 0) g_nsq[b * SS + i] = sum;
                else g_dots[((size_t)b * RAD + (d - 1)) * SS + i] = sum;
            }
        }
    }
}

// ---------------------------------------------------------------------------
// mu: 8 threads per edge, CONFLICT-FREE strided channels (k = sub*4 + m*32).
// Lanes 0-7 read consecutive float4s (128 B span); lanes 8-31 broadcast.
// ---------------------------------------------------------------------------
__global__ __launch_bounds__(256) void mu_kernel4(
    const float* __restrict__ W1, const float* __restrict__ b1,
    const float* __restrict__ W2, const float* __restrict__ b2)
{
    __shared__ float w1a[INNERD], w1b[INNERD], bb1[INNERD], w2s[INNERD];
    int tid = threadIdx.x;
#pragma unroll
    for (int r = 0; r < 2; r++) {
        int k = tid + 256 * r;
        w1a[k] = W1[k];
        w1b[k] = W1[INNERD + k];
        bb1[k] = b1[k];
        w2s[k] = W2[k];
    }
    __syncthreads();

    int e = blockIdx.x * 32 + (tid >> 3);     // edge id
    int sub = tid & 7;
    int b = e >> 14;
    int r = e & 16383;
    int d = (r >> 11) + 1;
    int i = r & 2047;
    size_t slot = ((size_t)b * RAD + (d - 1)) * SS + i;
    bool valid = (i + d < SS);

    int j = valid ? (i + d) : i;
    float nsqi = g_nsq[b * SS + i];
    float nsqj = g_nsq[b * SS + j];
    float dot  = valid ? g_dots[slot] : 0.f;
    float dist = sqrtf(fmaxf(nsqi + nsqj - 2.f * dot, 0.f));
    float ni = fmaxf(sqrtf(nsqi), 1e-6f);
    float nj = fmaxf(sqrtf(nsqj), 1e-6f);
    float cosv = dot / (ni * nj);

    float z = 0.f;
#pragma unroll
    for (int m = 0; m < INNERD / 32; m++) {     // 16 iters
        int k = sub * 4 + m * 32;               // conflict-free across sub
        float4 wa = *(const float4*)&w1a[k];
        float4 wb = *(const float4*)&w1b[k];
        float4 bv = *(const float4*)&bb1[k];
        float4 w2v = *(const float4*)&w2s[k];
        float x0 = fmaf(dist, wa.x, fmaf(cosv, wb.x, bv.x));
        float x1 = fmaf(dist, wa.y, fmaf(cosv, wb.y, bv.y));
        float x2 = fmaf(dist, wa.z, fmaf(cosv, wb.z, bv.z));
        float x3 = fmaf(dist, wa.w, fmaf(cosv, wb.w, bv.w));
        float g0 = fmaxf(x0, 0.f);
        float g1 = fmaxf(x1, 0.f);
        float g2 = fmaxf(x2, 0.f);
        float g3 = fmaxf(x3, 0.f);
        if (fabsf(x0) < 6.f) g0 = 0.5f*x0*(1.f + erff(x0 * 0.70710678118654752f));
        if (fabsf(x1) < 6.f) g1 = 0.5f*x1*(1.f + erff(x1 * 0.70710678118654752f));
        if (fabsf(x2) < 6.f) g2 = 0.5f*x2*(1.f + erff(x2 * 0.70710678118654752f));
        if (fabsf(x3) < 6.f) g3 = 0.5f*x3*(1.f + erff(x3 * 0.70710678118654752f));
        z = fmaf(g0, w2v.x, z);
        z = fmaf(g1, w2v.y, z);
        z = fmaf(g2, w2v.z, z);
        z = fmaf(g3, w2v.w, z);
    }
    z += __shfl_xor_sync(0xffffffffu, z, 1);
    z += __shfl_xor_sync(0xffffffffu, z, 2);
    z += __shfl_xor_sync(0xffffffffu, z, 4);
    if (sub == 0) {
        if (!valid) { g_mu[slot] = 0.f; return; }
        float zz = z + b2[0];
        float sp = fmaxf(zz, 0.f) + log1pf(expf(-fabsf(zz)));
        g_mu[slot] = fminf(sp + 1e-5f, MU_MAXV);
    }
}

// ---------------------------------------------------------------------------
// Fused deg+lap+update+smooth. src -> dst (ping-pong, race-free).
// Tile = 16 output rows; state rows [i0-9, i0+25) (34), tmp rows (18).
// ---------------------------------------------------------------------------
#define LT 16
#define LSROWS 34
#define LTROWS 18
#define LAPS_SMEM (((size_t)LSROWS * HH + (size_t)LTROWS * HH + \
                    LTROWS * 16 + LTROWS + LSROWS) * sizeof(float))

__global__ __launch_bounds__(256) void lapsmooth_kernel(
    const float* __restrict__ src, float* __restrict__ dst, float eta)
{
    extern __shared__ float sh[];
    float* st   = sh;                                 // LSROWS * HH
    float* tp   = st + (size_t)LSROWS * HH;           // LTROWS * HH
    float* cof  = tp + (size_t)LTROWS * HH;           // LTROWS * 16
    float* csm  = cof + LTROWS * 16;                  // LTROWS
    float* isqs = csm + LTROWS;                       // LSROWS

    int tid = threadIdx.x;
    int b = blockIdx.y;
    int i0 = blockIdx.x * LT;

    // load state rows [i0-9, i0+25)
#pragma unroll
    for (int r = 0; r < LSROWS; r++) {
        int j = i0 - 9 + r;
        if (j >= 0 && j < SS)
            ((float4*)(st + (size_t)r * HH))[tid] =
                ((const float4*)(src + ((size_t)b * SS + j) * HH))[tid];
    }
    // fused deg: isq for nodes [i0-9, i0+25)
    if (tid < LSROWS) {
        int n = i0 - 9 + tid;
        float isq = 0.f;
        if (n >= 0 && n < SS) {
            float deg = 0.f;
#pragma unroll
            for (int d = 1; d <= RAD; d++) {
                if (n + d < SS) deg += g_mu[((size_t)b * RAD + (d - 1)) * SS + n];
                if (n >= d)     deg += g_mu[((size_t)b * RAD + (d - 1)) * SS + n - d];
            }
            isq = rsqrtf(fmaxf(deg, 1e-6f));
        }
        isqs[tid] = isq;
    }
    __syncthreads();

    // coefficients for 18 tmp rows (clamped j)
    for (int idx = tid; idx < LTROWS * 16; idx += 256) {
        int jl = idx >> 4;
        int k = idx & 15;
        int j = i0 - 1 + jl;
        int je = min(max(j, 0), SS - 1);
        int d = (k >> 1) + 1;
        float c = 0.f;
        if (!(k & 1)) {                       // + direction
            int jn = je + d;
            if (jn < SS)
                c = g_mu[((size_t)b * RAD + (d - 1)) * SS + je] *
                    isqs[je - (i0 - 9)] * isqs[jn - (i0 - 9)];
        } else {                              // - direction
            int jn = je - d;
            if (jn >= 0)
                c = g_mu[((size_t)b * RAD + (d - 1)) * SS + jn] *
                    isqs[je - (i0 - 9)] * isqs[jn - (i0 - 9)];
        }
        cof[idx] = c;
    }
    __syncthreads();
    if (tid < LTROWS) {
        float s = 0.f;
#pragma unroll
        for (int k = 0; k < 16; k++) s += cof[tid * 16 + k];
        csm[tid] = s;
    }
    __syncthreads();

    // tmp rows
#pragma unroll
    for (int jl = 0; jl < LTROWS; jl++) {
        int j = i0 - 1 + jl;
        int je = min(max(j, 0), SS - 1);
        int jloc = je - i0 + 9;              // local state index
        float4 si = ((const float4*)(st + (size_t)jloc * HH))[tid];
        float cs = csm[jl];
        float4 acc;
        acc.x = cs * si.x; acc.y = cs * si.y; acc.z = cs * si.z; acc.w = cs * si.w;
#pragma unroll
        for (int k = 0; k < 16; k++) {
            float c = cof[jl * 16 + k];
            if (c != 0.f) {
                int d = (k >> 1) + 1;
                int off = (k & 1) ? -d : d;
                float4 sj = ((const float4*)(st + (size_t)(jloc + off) * HH))[tid];
                acc.x = fmaf(-c, sj.x, acc.x);
                acc.y = fmaf(-c, sj.y, acc.y);
                acc.z = fmaf(-c, sj.z, acc.z);
                acc.w = fmaf(-c, sj.w, acc.w);
            }
        }
        float4 qv = ((const float4*)(g_q + ((size_t)b * SS + je) * HH))[tid];
        float4 tv;
        tv.x = si.x - eta * (acc.x - qv.x);
        tv.y = si.y - eta * (acc.y - qv.y);
        tv.z = si.z - eta * (acc.z - qv.z);
        tv.w = si.w - eta * (acc.w - qv.w);
        ((float4*)(tp + (size_t)jl * HH))[tid] = tv;
    }
    __syncthreads();

    // smooth + writeback
#pragma unroll
    for (int il = 0; il < LT; il++) {
        int i = i0 + il;
        if (i >= SS) break;
        int jl = il + 1;
        float4 s = ((const float4*)(tp + (size_t)jl * HH))[tid];
        float4 l = ((const float4*)(tp + (size_t)(jl - 1) * HH))[tid];
        float4 r = ((const float4*)(tp + (size_t)(jl + 1) * HH))[tid];
        float4 o;
        o.x = s.x - LAMv * (2.f * s.x - l.x - r.x);
        o.y = s.y - LAMv * (2.f * s.y - l.y - r.y);
        o.z = s.z - LAMv * (2.f * s.z - l.z - r.z);
        o.w = s.w - LAMv * (2.f * s.w - l.w - r.w);
        ((float4*)(dst + ((size_t)b * SS + i) * HH))[tid] = o;
    }
}

// ---------------------------------------------------------------------------
// Zero energy slots (out[BSH .. BSH+BB))
// ---------------------------------------------------------------------------
__global__ void zero_energy_kernel(float* __restrict__ out)
{
    if (threadIdx.x < BB) out[(size_t)BSH + threadIdx.x] = 0.f;
}

// ---------------------------------------------------------------------------
// Fused final energy: per tile, energy += 0.5 * sum mu_e * ||s_i - s_j||^2.
// ---------------------------------------------------------------------------
__global__ __launch_bounds__(256) void energy_tiled_kernel(
    const float* __restrict__ src, float* __restrict__ out)
{
    extern __shared__ float sh[];  // DROWS * HH
    int tid = threadIdx.x;
    int b = blockIdx.y;
    int i0 = blockIdx.x * DT;

#pragma unroll
    for (int r = 0; r < DROWS; r++) {
        int i = i0 + r;
        if (i < SS)
            ((float4*)(sh + (size_t)r * HH))[tid] =
                ((const float4*)(src + ((size_t)b * SS + i) * HH))[tid];
    }
    __syncthreads();

    int w = tid >> 5, lane = tid & 31;
    float wpart = 0.f;
#pragma unroll
    for (int nn = 0; nn < 3; nn++) {
        int ln = w * 3 + nn;
        int i = i0 + ln;
        if (i >= SS) continue;
        const float4* arow = (const float4*)(sh + (size_t)ln * HH);
        float4 a[8];
#pragma unroll
        for (int r = 0; r < 8; r++) a[r] = arow[lane + 32 * r];
#pragma unroll
        for (int d = 1; d <= RAD; d++) {
            if (i + d >= SS) break;
            const float4* crow = (const float4*)(sh + (size_t)(ln + d) * HH);
            float sum = 0.f;
#pragma unroll
            for (int r = 0; r < 8; r++) {
                float4 c = crow[lane + 32 * r];
                float dx = a[r].x - c.x, dy = a[r].y - c.y;
                float dz = a[r].z - c.z, dw = a[r].w - c.w;
                sum += dx*dx + dy*dy + dz*dz + dw*dw;
            }
#pragma unroll
            for (int o = 16; o > 0; o >>= 1)
                sum += __shfl_xor_sync(0xffffffffu, sum, o);
            if (lane == 0)
                wpart += g_mu[((size_t)b * RAD + (d - 1)) * SS + i] * sum;
        }
    }
    __shared__ float red[8];
    if (lane == 0) red[w] = wpart;
    __syncthreads();
    if (tid == 0) {
        float s = 0.f;
#pragma unroll
        for (int ww = 0; ww < 8; ww++) s += red[ww];
        atomicAdd(&out[(size_t)BSH + b], 0.5f * s);
    }
}

// ---------------------------------------------------------------------------
// out = layernorm(final + hidden) * gamma + beta
// ---------------------------------------------------------------------------
__global__ __launch_bounds__(256) void ln_kernel(
    const float* __restrict__ fin,
    const float* __restrict__ hidden,
    const float* __restrict__ gamma, const float* __restrict__ beta,
    float* __restrict__ out)
{
    int i = blockIdx.x, b = blockIdx.y;
    int tid = threadIdx.x;
    size_t base = ((size_t)b * SS + i) * HH + tid * 4;
    float4 s = *(const float4*)&fin[base];
    float4 h = *(const float4*)&hidden[base];
    float4 x;
    x.x = s.x + h.x; x.y = s.y + h.y; x.z = s.z + h.z; x.w = s.w + h.w;
    float sum = x.x + x.y + x.z + x.w;
    float sq  = x.x*x.x + x.y*x.y + x.z*x.z + x.w*x.w;
#pragma unroll
    for (int o = 16; o > 0; o >>= 1) {
        sum += __shfl_xor_sync(0xffffffffu, sum, o);
        sq  += __shfl_xor_sync(0xffffffffu, sq,  o);
    }
    __shared__ float rs[8], rq[8];
    int wid = tid >> 5, lane = tid & 31;
    if (lane == 0) { rs[wid] = sum; rq[wid] = sq; }
    __syncthreads();
    __shared__ float s_mean, s_rstd;
    if (tid == 0) {
        float ts = 0.f, tq = 0.f;
#pragma unroll
        for (int w = 0; w < 8; w++) { ts += rs[w]; tq += rq[w]; }
        float mean = ts / HH;
        float var = tq / HH - mean * mean;
        s_mean = mean;
        s_rstd = rsqrtf(var + 1e-5f);
    }
    __syncthreads();
    float mean = s_mean, rstd = s_rstd;
    int hbase = tid * 4;
    float4 o;
    o.x = (x.x - mean) * rstd * gamma[hbase+0] + beta[hbase+0];
    o.y = (x.y - mean) * rstd * gamma[hbase+1] + beta[hbase+1];
    o.z = (x.z - mean) * rstd * gamma[hbase+2] + beta[hbase+2];
    o.w = (x.w - mean) * rstd * gamma[hbase+3] + beta[hbase+3];
    *(float4*)&out[base] = o;
}

// ---------------------------------------------------------------------------
extern "C" void kernel_launch(void* const* d_in, const int* in_sizes, int n_in,
                              void* d_out, int out_size)
{
    const float* hidden = (const float*)d_in[0];
    const float* Wq = (const float*)d_in[3];
    const float* bq = (const float*)d_in[4];
    const float* W1 = (const float*)d_in[5];
    const float* b1 = (const float*)d_in[6];
    const float* W2 = (const float*)d_in[7];
    const float* b2 = (const float*)d_in[8];
    const float* gamma = (const float*)d_in[9];
    const float* beta  = (const float*)d_in[10];
    float* out = (float*)d_out;

    float *pA = nullptr, *pB = nullptr;
    cudaGetSymbolAddress((void**)&pA, g_stateA);
    cudaGetSymbolAddress((void**)&pB, g_stateB);

    cudaFuncSetAttribute(dots_tiled_kernel,
                         cudaFuncAttributeMaxDynamicSharedMemorySize, DOTS_SMEM);
    cudaFuncSetAttribute(energy_tiled_kernel,
                         cudaFuncAttributeMaxDynamicSharedMemorySize, DOTS_SMEM);
    cudaFuncSetAttribute(lapsmooth_kernel,
                         cudaFuncAttributeMaxDynamicSharedMemorySize, LAPS_SMEM);

    gemm_tf32_kernel<<<dim3(HH / TN, (BB * SS) / TM), 256>>>(hidden, Wq, bq);
    zero_energy_kernel<<<1, 32>>>(out);

    // ping-pong: hidden -> A -> B -> A -> B
    const float* srcs[KSTEPS + 1] = { hidden, pA, pB, pA, pB };
    float*       dsts[KSTEPS]     = { pA, pB, pA, pB };

    const int dots_grid = (SS + DT - 1) / DT;   // 86
    float eta = 0.1f;
    for (int step = 0; step < KSTEPS; step++) {
        dots_tiled_kernel<<<dim3(dots_grid, BB), 256, DOTS_SMEM>>>(srcs[step]);
        mu_kernel4<<<(BB * RAD * SS) / 32, 256>>>(W1, b1, W2, b2);
        lapsmooth_kernel<<<dim3(SS / LT, BB), 256, LAPS_SMEM>>>(srcs[step], dsts[step], eta);
        eta *= 0.9f;
    }
    energy_tiled_kernel<<<dim3(dots_grid, BB), 256, DOTS_SMEM>>>(srcs[KSTEPS], out);
    ln_kernel<<<dim3(SS, BB), 256>>>(srcs[KSTEPS], hidden, gamma, beta, out);
}

// round 8
// speedup vs baseline: 1.6339x; 1.1294x over previous
#include <cuda_runtime.h>
#include <math.h>
#include <stdint.h>

#define BB 4
#define SS 2048
#define HH 1024
#define INNERD 512
#define RAD 8
#define KSTEPS 4
#define LAMv 0.1f
#define MU_MAXV 10.0f

#define BSH (BB*SS*HH)

// Scratch (no cudaMalloc allowed). Ping-pong state buffers.
__device__ float g_q[BSH];
__device__ float g_stateA[BSH];
__device__ float g_stateB[BSH];
__device__ float g_nsq[BB*SS];
__device__ float g_dots[BB*RAD*SS];
__device__ float g_mu[BB*RAD*SS];

__device__ __forceinline__ float to_tf32(float x) {
    float r;
    asm("cvt.rna.tf32.f32 %0, %1;" : "=f"(r) : "f"(x));
    return r;
}
__device__ __forceinline__ uint32_t tf32_bits(float x) {
    return __float_as_uint(to_tf32(x));
}
__device__ __forceinline__ void cp_async16(uint32_t s, const void* g) {
    asm volatile("cp.async.ca.shared.global [%0], [%1], 16;" :: "r"(s), "l"(g));
}
__device__ __forceinline__ void cp_commit() {
    asm volatile("cp.async.commit_group;");
}
template<int N>
__device__ __forceinline__ void cp_wait() {
    asm volatile("cp.async.wait_group %0;" :: "n"(N));
}

// ---------------------------------------------------------------------------
// GEMM (TF32 mma.sync, cp.async double-buffered): q = hidden @ Wq + bq.
// Block 128x128, 8 warps (warp 32x64), K-step 32, 2 stages.
// cvt.rna applied at register load (keeps fp32->tf32 round-to-nearest).
// ---------------------------------------------------------------------------
#define TM 128
#define TN 128
#define TK 32
#define AS_LD (TK + 4)    // As[m][k] row length (36)
#define BS_LD (TN + 4)    // Bs[k][n] row length (132)
#define AS_STAGE (TM * AS_LD)
#define BS_STAGE (TK * BS_LD)
#define GEMM_SMEM ((2*AS_STAGE + 2*BS_STAGE) * sizeof(float))

__global__ __launch_bounds__(256) void gemm_tf32_kernel(
    const float* __restrict__ A,
    const float* __restrict__ W,
    const float* __restrict__ bias)
{
    extern __shared__ float sm[];
    float* As = sm;                       // 2 stages, [m][k]
    float* Bs = sm + 2 * AS_STAGE;        // 2 stages, [k][n]
    uint32_t as_u = (uint32_t)__cvta_generic_to_shared(As);
    uint32_t bs_u = (uint32_t)__cvta_generic_to_shared(Bs);

    const int N = HH, K = HH;
    int tid = threadIdx.x;
    int m0 = blockIdx.y * TM;
    int n0 = blockIdx.x * TN;
    int wid = tid >> 5, lane = tid & 31;
    int wm = (wid & 3) * 32;
    int wn = (wid >> 2) * 64;
    int gid = lane >> 2, tig = lane & 3;

    float acc[2][8][4];
#pragma unroll
    for (int mt = 0; mt < 2; mt++)
#pragma unroll
        for (int nt = 0; nt < 8; nt++)
#pragma unroll
            for (int c = 0; c < 4; c++) acc[mt][nt][c] = 0.f;

    int am[4], ak[4], bk[4], bn[4];
#pragma unroll
    for (int r = 0; r < 4; r++) {
        int f = tid + 256 * r;
        am[r] = f >> 3;  ak[r] = (f & 7) * 4;
        bk[r] = f >> 5;  bn[r] = (f & 31) * 4;
    }

#define LOAD_STAGE(s, k0)                                                     \
    {                                                                         \
        _Pragma("unroll")                                                     \
        for (int r = 0; r < 4; r++) {                                         \
            cp_async16(as_u + (((s)*TM + am[r]) * AS_LD + ak[r]) * 4,         \
                       &A[(size_t)(m0 + am[r]) * K + (k0) + ak[r]]);          \
            cp_async16(bs_u + (((s)*TK + bk[r]) * BS_LD + bn[r]) * 4,         \
                       &W[(size_t)((k0) + bk[r]) * N + n0 + bn[r]]);          \
        }                                                                     \
        cp_commit();                                                          \
    }

    LOAD_STAGE(0, 0);

    const int NIT = K / TK;   // 32
    for (int it = 0; it < NIT; it++) {
        if (it + 1 < NIT) {
            LOAD_STAGE((it + 1) & 1, (it + 1) * TK);
            cp_wait<1>();
        } else {
            cp_wait<0>();
        }
        __syncthreads();

        int buf = it & 1;
        const float* Ab = As + buf * AS_STAGE;
        const float* Bb = Bs + buf * BS_STAGE;
#pragma unroll
        for (int ks = 0; ks < 4; ks++) {
            int kb = ks * 8;
            uint32_t af[2][4];
#pragma unroll
            for (int mt = 0; mt < 2; mt++) {
                int rm = wm + mt * 16 + gid;
                af[mt][0] = tf32_bits(Ab[rm * AS_LD + kb + tig]);
                af[mt][1] = tf32_bits(Ab[(rm + 8) * AS_LD + kb + tig]);
                af[mt][2] = tf32_bits(Ab[rm * AS_LD + kb + tig + 4]);
                af[mt][3] = tf32_bits(Ab[(rm + 8) * AS_LD + kb + tig + 4]);
            }
            uint32_t bf[8][2];
#pragma unroll
            for (int nt = 0; nt < 8; nt++) {
                int cn = wn + nt * 8 + gid;
                bf[nt][0] = tf32_bits(Bb[(kb + tig) * BS_LD + cn]);
                bf[nt][1] = tf32_bits(Bb[(kb + tig + 4) * BS_LD + cn]);
            }
#pragma unroll
            for (int mt = 0; mt < 2; mt++)
#pragma unroll
                for (int nt = 0; nt < 8; nt++) {
                    asm volatile(
                        "mma.sync.aligned.m16n8k8.row.col.f32.tf32.tf32.f32 "
                        "{%0,%1,%2,%3}, {%4,%5,%6,%7}, {%8,%9}, {%0,%1,%2,%3};"
                        : "+f"(acc[mt][nt][0]), "+f"(acc[mt][nt][1]),
                          "+f"(acc[mt][nt][2]), "+f"(acc[mt][nt][3])
                        : "r"(af[mt][0]), "r"(af[mt][1]),
                          "r"(af[mt][2]), "r"(af[mt][3]),
                          "r"(bf[nt][0]), "r"(bf[nt][1]));
                }
        }
        __syncthreads();
    }

#pragma unroll
    for (int mt = 0; mt < 2; mt++) {
        int row0 = m0 + wm + mt * 16 + gid;
#pragma unroll
        for (int nt = 0; nt < 8; nt++) {
            int col = n0 + wn + nt * 8 + 2 * tig;
            float bx = bias[col], by = bias[col + 1];
            float2 v0 = make_float2(acc[mt][nt][0] + bx, acc[mt][nt][1] + by);
            float2 v1 = make_float2(acc[mt][nt][2] + bx, acc[mt][nt][3] + by);
            *(float2*)&g_q[(size_t)row0 * N + col] = v0;
            *(float2*)&g_q[(size_t)(row0 + 8) * N + col] = v1;
        }
    }
}

// ---------------------------------------------------------------------------
// Tiled dots: block = 24 nodes (+8 halo rows). nsq + dots[d=1..8].
// ---------------------------------------------------------------------------
#define DT 24
#define DROWS 32
#define DOTS_SMEM (DROWS * HH * sizeof(float))

__global__ __launch_bounds__(256) void dots_tiled_kernel(const float* __restrict__ src)
{
    extern __shared__ float sh[];  // DROWS * HH
    int tid = threadIdx.x;
    int b = blockIdx.y;
    int i0 = blockIdx.x * DT;

#pragma unroll
    for (int r = 0; r < DROWS; r++) {
        int i = i0 + r;
        if (i < SS)
            ((float4*)(sh + (size_t)r * HH))[tid] =
                ((const float4*)(src + ((size_t)b * SS + i) * HH))[tid];
    }
    __syncthreads();

    int w = tid >> 5, lane = tid & 31;
#pragma unroll
    for (int nn = 0; nn < 3; nn++) {
        int ln = w * 3 + nn;          // 0..23
        int i = i0 + ln;
        if (i >= SS) continue;
        const float4* arow = (const float4*)(sh + (size_t)ln * HH);
        float4 a[8];
#pragma unroll
        for (int r = 0; r < 8; r++) a[r] = arow[lane + 32 * r];

#pragma unroll
        for (int d = 0; d <= RAD; d++) {
            if (d > 0 && i + d >= SS) break;
            float sum = 0.f;
            if (d == 0) {
#pragma unroll
                for (int r = 0; r < 8; r++)
                    sum += a[r].x*a[r].x + a[r].y*a[r].y + a[r].z*a[r].z + a[r].w*a[r].w;
            } else {
                const float4* crow = (const float4*)(sh + (size_t)(ln + d) * HH);
#pragma unroll
                for (int r = 0; r < 8; r++) {
                    float4 c = crow[lane + 32 * r];
                    sum += a[r].x*c.x + a[r].y*c.y + a[r].z*c.z + a[r].w*c.w;
                }
            }
#pragma unroll
            for (int o = 16; o > 0; o >>= 1)
                sum += __shfl_xor_sync(0xffffffffu, sum, o);
            if (lane == 0) {
                if (d == 0) g_nsq[b * SS + i] = sum;
                else g_dots[((size_t)b * RAD + (d - 1)) * SS + i] = sum;
            }
        }
    }
}

// ---------------------------------------------------------------------------
// mu: 8 threads/edge, conflict-free strided channels, BRANCH-FREE gelu (erff
// unconditional: kills BSSY/BSYNC + FSETP alu traffic that bounded issue).
// ---------------------------------------------------------------------------
__global__ __launch_bounds__(256) void mu_kernel5(
    const float* __restrict__ W1, const float* __restrict__ b1,
    const float* __restrict__ W2, const float* __restrict__ b2)
{
    __shared__ float w1a[INNERD], w1b[INNERD], bb1[INNERD], w2s[INNERD];
    int tid = threadIdx.x;
#pragma unroll
    for (int r = 0; r < 2; r++) {
        int k = tid + 256 * r;
        w1a[k] = W1[k];
        w1b[k] = W1[INNERD + k];
        bb1[k] = b1[k];
        w2s[k] = W2[k];
    }
    __syncthreads();

    int e = blockIdx.x * 32 + (tid >> 3);     // edge id
    int sub = tid & 7;
    int b = e >> 14;
    int r = e & 16383;
    int d = (r >> 11) + 1;
    int i = r & 2047;
    size_t slot = ((size_t)b * RAD + (d - 1)) * SS + i;
    bool valid = (i + d < SS);

    int j = valid ? (i + d) : i;
    float nsqi = g_nsq[b * SS + i];
    float nsqj = g_nsq[b * SS + j];
    float dot  = valid ? g_dots[slot] : 0.f;
    float dist = sqrtf(fmaxf(nsqi + nsqj - 2.f * dot, 0.f));
    float ni = fmaxf(sqrtf(nsqi), 1e-6f);
    float nj = fmaxf(sqrtf(nsqj), 1e-6f);
    float cosv = dot / (ni * nj);

    const float IS2 = 0.70710678118654752f;
    float z = 0.f;
#pragma unroll
    for (int m = 0; m < INNERD / 32; m++) {     // 16 iters
        int k = sub * 4 + m * 32;               // conflict-free across sub
        float4 wa = *(const float4*)&w1a[k];
        float4 wb = *(const float4*)&w1b[k];
        float4 bv = *(const float4*)&bb1[k];
        float4 w2v = *(const float4*)&w2s[k];
        float x0 = fmaf(dist, wa.x, fmaf(cosv, wb.x, bv.x));
        float x1 = fmaf(dist, wa.y, fmaf(cosv, wb.y, bv.y));
        float x2 = fmaf(dist, wa.z, fmaf(cosv, wb.z, bv.z));
        float x3 = fmaf(dist, wa.w, fmaf(cosv, wb.w, bv.w));
        float g0 = 0.5f * x0 * (1.f + erff(x0 * IS2));
        float g1 = 0.5f * x1 * (1.f + erff(x1 * IS2));
        float g2 = 0.5f * x2 * (1.f + erff(x2 * IS2));
        float g3 = 0.5f * x3 * (1.f + erff(x3 * IS2));
        z = fmaf(g0, w2v.x, z);
        z = fmaf(g1, w2v.y, z);
        z = fmaf(g2, w2v.z, z);
        z = fmaf(g3, w2v.w, z);
    }
    z += __shfl_xor_sync(0xffffffffu, z, 1);
    z += __shfl_xor_sync(0xffffffffu, z, 2);
    z += __shfl_xor_sync(0xffffffffu, z, 4);
    if (sub == 0) {
        if (!valid) { g_mu[slot] = 0.f; return; }
        float zz = z + b2[0];
        float sp = fmaxf(zz, 0.f) + log1pf(expf(-fabsf(zz)));
        g_mu[slot] = fminf(sp + 1e-5f, MU_MAXV);
    }
}

// ---------------------------------------------------------------------------
// Fused deg+lap+update+smooth, register-rolling tmp (R3 structure + deg fuse).
// LT=32 output rows, 50 state rows in smem; 512 threads, float2 per thread.
// ---------------------------------------------------------------------------
#define LT 32
#define LSROWS (LT + 18)     // 50
#define LTROWS (LT + 2)      // 34
#define LAPS_SMEM (((size_t)LSROWS * HH + LTROWS * 16 + LTROWS + LSROWS) * sizeof(float))

__global__ __launch_bounds__(512) void lapsmooth_kernel(
    const float* __restrict__ src, float* __restrict__ dst, float eta)
{
    extern __shared__ float sh[];
    float* st   = sh;                         // LSROWS * HH
    float* cof  = st + (size_t)LSROWS * HH;   // LTROWS * 16
    float* csm  = cof + LTROWS * 16;          // LTROWS
    float* isqs = csm + LTROWS;               // LSROWS (nodes i0-9 .. i0+40)

    int tid = threadIdx.x;
    int b = blockIdx.y;
    int i0 = blockIdx.x * LT;
    int c2 = tid * 2;                         // column pair

    // load state rows [i0-9, i0+41)
#pragma unroll
    for (int r = 0; r < LSROWS; r++) {
        int j = i0 - 9 + r;
        if (j >= 0 && j < SS)
            *(float2*)&st[(size_t)r * HH + c2] =
                *(const float2*)&src[((size_t)b * SS + j) * HH + c2];
    }
    // fused deg: isq for nodes [i0-9, i0+41)
    if (tid < LSROWS) {
        int n = i0 - 9 + tid;
        float isq = 0.f;
        if (n >= 0 && n < SS) {
            float deg = 0.f;
#pragma unroll
            for (int d = 1; d <= RAD; d++) {
                if (n + d < SS) deg += g_mu[((size_t)b * RAD + (d - 1)) * SS + n];
                if (n >= d)     deg += g_mu[((size_t)b * RAD + (d - 1)) * SS + n - d];
            }
            isq = rsqrtf(fmaxf(deg, 1e-6f));
        }
        isqs[tid] = isq;
    }
    __syncthreads();

    // coefficients for LTROWS tmp rows (clamped je)
    for (int idx = tid; idx < LTROWS * 16; idx += 512) {
        int jl = idx >> 4;
        int k = idx & 15;
        int j = i0 - 1 + jl;
        int je = min(max(j, 0), SS - 1);
        int d = (k >> 1) + 1;
        float c = 0.f;
        if (!(k & 1)) {
            int jn = je + d;
            if (jn < SS)
                c = g_mu[((size_t)b * RAD + (d - 1)) * SS + je] *
                    isqs[je - (i0 - 9)] * isqs[jn - (i0 - 9)];
        } else {
            int jn = je - d;
            if (jn >= 0)
                c = g_mu[((size_t)b * RAD + (d - 1)) * SS + jn] *
                    isqs[je - (i0 - 9)] * isqs[jn - (i0 - 9)];
        }
        cof[idx] = c;
    }
    __syncthreads();
    if (tid < LTROWS) {
        float s = 0.f;
#pragma unroll
        for (int k = 0; k < 16; k++) s += cof[tid * 16 + k];
        csm[tid] = s;
    }
    __syncthreads();

    float2 t0, t1, t2;
#pragma unroll
    for (int jl = 0; jl < LTROWS; jl++) {
        int j = i0 - 1 + jl;
        int je = min(max(j, 0), SS - 1);
        int jloc = je - i0 + 9;
        float2 si = *(const float2*)&st[(size_t)jloc * HH + c2];
        float cs = csm[jl];
        float2 acc;
        acc.x = cs * si.x; acc.y = cs * si.y;
#pragma unroll
        for (int k = 0; k < 16; k++) {
            float c = cof[jl * 16 + k];
            if (c != 0.f) {
                int d = (k >> 1) + 1;
                int off = (k & 1) ? -d : d;
                float2 sj = *(const float2*)&st[(size_t)(jloc + off) * HH + c2];
                acc.x = fmaf(-c, sj.x, acc.x);
                acc.y = fmaf(-c, sj.y, acc.y);
            }
        }
        float2 qv = *(const float2*)&g_q[((size_t)b * SS + je) * HH + c2];
        float2 tv;
        tv.x = si.x - eta * (acc.x - qv.x);
        tv.y = si.y - eta * (acc.y - qv.y);
        t0 = t1; t1 = t2; t2 = tv;
        if (jl >= 2) {
            int i = i0 + jl - 2;
            float2 o;
            o.x = t1.x - LAMv * (2.f * t1.x - t0.x - t2.x);
            o.y = t1.y - LAMv * (2.f * t1.y - t0.y - t2.y);
            *(float2*)&dst[((size_t)b * SS + i) * HH + c2] = o;
        }
    }
}

// ---------------------------------------------------------------------------
// Zero energy slots (out[BSH .. BSH+BB))
// ---------------------------------------------------------------------------
__global__ void zero_energy_kernel(float* __restrict__ out)
{
    if (threadIdx.x < BB) out[(size_t)BSH + threadIdx.x] = 0.f;
}

// ---------------------------------------------------------------------------
// Fused final energy: per tile, energy += 0.5 * sum mu_e * ||s_i - s_j||^2.
// ---------------------------------------------------------------------------
__global__ __launch_bounds__(256) void energy_tiled_kernel(
    const float* __restrict__ src, float* __restrict__ out)
{
    extern __shared__ float sh[];  // DROWS * HH
    int tid = threadIdx.x;
    int b = blockIdx.y;
    int i0 = blockIdx.x * DT;

#pragma unroll
    for (int r = 0; r < DROWS; r++) {
        int i = i0 + r;
        if (i < SS)
            ((float4*)(sh + (size_t)r * HH))[tid] =
                ((const float4*)(src + ((size_t)b * SS + i) * HH))[tid];
    }
    __syncthreads();

    int w = tid >> 5, lane = tid & 31;
    float wpart = 0.f;
#pragma unroll
    for (int nn = 0; nn < 3; nn++) {
        int ln = w * 3 + nn;
        int i = i0 + ln;
        if (i >= SS) continue;
        const float4* arow = (const float4*)(sh + (size_t)ln * HH);
        float4 a[8];
#pragma unroll
        for (int r = 0; r < 8; r++) a[r] = arow[lane + 32 * r];
#pragma unroll
        for (int d = 1; d <= RAD; d++) {
            if (i + d >= SS) break;
            const float4* crow = (const float4*)(sh + (size_t)(ln + d) * HH);
            float sum = 0.f;
#pragma unroll
            for (int r = 0; r < 8; r++) {
                float4 c = crow[lane + 32 * r];
                float dx = a[r].x - c.x, dy = a[r].y - c.y;
                float dz = a[r].z - c.z, dw = a[r].w - c.w;
                sum += dx*dx + dy*dy + dz*dz + dw*dw;
            }
#pragma unroll
            for (int o = 16; o > 0; o >>= 1)
                sum += __shfl_xor_sync(0xffffffffu, sum, o);
            if (lane == 0)
                wpart += g_mu[((size_t)b * RAD + (d - 1)) * SS + i] * sum;
        }
    }
    __shared__ float red[8];
    if (lane == 0) red[w] = wpart;
    __syncthreads();
    if (tid == 0) {
        float s = 0.f;
#pragma unroll
        for (int ww = 0; ww < 8; ww++) s += red[ww];
        atomicAdd(&out[(size_t)BSH + b], 0.5f * s);
    }
}

// ---------------------------------------------------------------------------
// out = layernorm(final + hidden) * gamma + beta
// ---------------------------------------------------------------------------
__global__ __launch_bounds__(256) void ln_kernel(
    const float* __restrict__ fin,
    const float* __restrict__ hidden,
    const float* __restrict__ gamma, const float* __restrict__ beta,
    float* __restrict__ out)
{
    int i = blockIdx.x, b = blockIdx.y;
    int tid = threadIdx.x;
    size_t base = ((size_t)b * SS + i) * HH + tid * 4;
    float4 s = *(const float4*)&fin[base];
    float4 h = *(const float4*)&hidden[base];
    float4 x;
    x.x = s.x + h.x; x.y = s.y + h.y; x.z = s.z + h.z; x.w = s.w + h.w;
    float sum = x.x + x.y + x.z + x.w;
    float sq  = x.x*x.x + x.y*x.y + x.z*x.z + x.w*x.w;
#pragma unroll
    for (int o = 16; o > 0; o >>= 1) {
        sum += __shfl_xor_sync(0xffffffffu, sum, o);
        sq  += __shfl_xor_sync(0xffffffffu, sq,  o);
    }
    __shared__ float rs[8], rq[8];
    int wid = tid >> 5, lane = tid & 31;
    if (lane == 0) { rs[wid] = sum; rq[wid] = sq; }
    __syncthreads();
    __shared__ float s_mean, s_rstd;
    if (tid == 0) {
        float ts = 0.f, tq = 0.f;
#pragma unroll
        for (int w = 0; w < 8; w++) { ts += rs[w]; tq += rq[w]; }
        float mean = ts / HH;
        float var = tq / HH - mean * mean;
        s_mean = mean;
        s_rstd = rsqrtf(var + 1e-5f);
    }
    __syncthreads();
    float mean = s_mean, rstd = s_rstd;
    int hbase = tid * 4;
    float4 o;
    o.x = (x.x - mean) * rstd * gamma[hbase+0] + beta[hbase+0];
    o.y = (x.y - mean) * rstd * gamma[hbase+1] + beta[hbase+1];
    o.z = (x.z - mean) * rstd * gamma[hbase+2] + beta[hbase+2];
    o.w = (x.w - mean) * rstd * gamma[hbase+3] + beta[hbase+3];
    *(float4*)&out[base] = o;
}

// ---------------------------------------------------------------------------
extern "C" void kernel_launch(void* const* d_in, const int* in_sizes, int n_in,
                              void* d_out, int out_size)
{
    const float* hidden = (const float*)d_in[0];
    const float* Wq = (const float*)d_in[3];
    const float* bq = (const float*)d_in[4];
    const float* W1 = (const float*)d_in[5];
    const float* b1 = (const float*)d_in[6];
    const float* W2 = (const float*)d_in[7];
    const float* b2 = (const float*)d_in[8];
    const float* gamma = (const float*)d_in[9];
    const float* beta  = (const float*)d_in[10];
    float* out = (float*)d_out;

    float *pA = nullptr, *pB = nullptr;
    cudaGetSymbolAddress((void**)&pA, g_stateA);
    cudaGetSymbolAddress((void**)&pB, g_stateB);

    cudaFuncSetAttribute(gemm_tf32_kernel,
                         cudaFuncAttributeMaxDynamicSharedMemorySize, GEMM_SMEM);
    cudaFuncSetAttribute(dots_tiled_kernel,
                         cudaFuncAttributeMaxDynamicSharedMemorySize, DOTS_SMEM);
    cudaFuncSetAttribute(energy_tiled_kernel,
                         cudaFuncAttributeMaxDynamicSharedMemorySize, DOTS_SMEM);
    cudaFuncSetAttribute(lapsmooth_kernel,
                         cudaFuncAttributeMaxDynamicSharedMemorySize, LAPS_SMEM);

    gemm_tf32_kernel<<<dim3(HH / TN, (BB * SS) / TM), 256, GEMM_SMEM>>>(hidden, Wq, bq);
    zero_energy_kernel<<<1, 32>>>(out);

    // ping-pong: hidden -> A -> B -> A -> B
    const float* srcs[KSTEPS + 1] = { hidden, pA, pB, pA, pB };
    float*       dsts[KSTEPS]     = { pA, pB, pA, pB };

    const int dots_grid = (SS + DT - 1) / DT;   // 86
    float eta = 0.1f;
    for (int step = 0; step < KSTEPS; step++) {
        dots_tiled_kernel<<<dim3(dots_grid, BB), 256, DOTS_SMEM>>>(srcs[step]);
        mu_kernel5<<<(BB * RAD * SS) / 32, 256>>>(W1, b1, W2, b2);
        lapsmooth_kernel<<<dim3(SS / LT, BB), 512, LAPS_SMEM>>>(srcs[step], dsts[step], eta);
        eta *= 0.9f;
    }
    energy_tiled_kernel<<<dim3(dots_grid, BB), 256, DOTS_SMEM>>>(srcs[KSTEPS], out);
    ln_kernel<<<dim3(SS, BB), 256>>>(srcs[KSTEPS], hidden, gamma, beta, out);
}

// round 9
// speedup vs baseline: 1.6995x; 1.0402x over previous
#include <cuda_runtime.h>
#include <math.h>
#include <stdint.h>

#define BB 4
#define SS 2048
#define HH 1024
#define INNERD 512
#define RAD 8
#define KSTEPS 4
#define LAMv 0.1f
#define MU_MAXV 10.0f

#define BSH (BB*SS*HH)

// Scratch (no cudaMalloc allowed). Ping-pong state buffers.
__device__ float g_q[BSH];
__device__ float g_stateA[BSH];
__device__ float g_stateB[BSH];
__device__ float g_nsq[BB*SS];
__device__ float g_dots[BB*RAD*SS];
__device__ float g_mu[BB*RAD*SS];

__device__ __forceinline__ float to_tf32(float x) {
    float r;
    asm("cvt.rna.tf32.f32 %0, %1;" : "=f"(r) : "f"(x));
    return r;
}
__device__ __forceinline__ uint32_t tf32_bits(float x) {
    return __float_as_uint(to_tf32(x));
}
__device__ __forceinline__ void cp_async16(uint32_t s, const void* g) {
    asm volatile("cp.async.ca.shared.global [%0], [%1], 16;" :: "r"(s), "l"(g));
}
__device__ __forceinline__ void cp_commit() {
    asm volatile("cp.async.commit_group;");
}
template<int N>
__device__ __forceinline__ void cp_wait() {
    asm volatile("cp.async.wait_group %0;" :: "n"(N));
}

// Branchless GELU via Abramowitz-Stegun 7.1.26 erf (|eps|<=1.5e-7).
__device__ __forceinline__ float gelu_fast(float x) {
    const float IS2 = 0.70710678118654752f;
    float u  = x * IS2;
    float au = fabsf(u);
    float t  = __fdividef(1.f, fmaf(0.3275911f, au, 1.f));
    float p  = fmaf(fmaf(fmaf(fmaf(1.061405429f, t, -1.453152027f),
                              t, 1.421413741f),
                         t, -0.284496736f),
                    t, 0.254829592f) * t;
    float S  = p * __expf(-au * au);            // = 1 - erf(au); ->0 for large au
    float ev = copysignf(1.f - S, u);           // erf(u)
    return 0.5f * x * (1.f + ev);
}

// ---------------------------------------------------------------------------
// GEMM (TF32 mma.sync, cp.async double-buffered): q = hidden @ Wq + bq.
// ---------------------------------------------------------------------------
#define TM 128
#define TN 128
#define TK 32
#define AS_LD (TK + 4)
#define BS_LD (TN + 4)
#define AS_STAGE (TM * AS_LD)
#define BS_STAGE (TK * BS_LD)
#define GEMM_SMEM ((2*AS_STAGE + 2*BS_STAGE) * sizeof(float))

__global__ __launch_bounds__(256) void gemm_tf32_kernel(
    const float* __restrict__ A,
    const float* __restrict__ W,
    const float* __restrict__ bias)
{
    extern __shared__ float sm[];
    float* As = sm;
    float* Bs = sm + 2 * AS_STAGE;
    uint32_t as_u = (uint32_t)__cvta_generic_to_shared(As);
    uint32_t bs_u = (uint32_t)__cvta_generic_to_shared(Bs);

    const int N = HH, K = HH;
    int tid = threadIdx.x;
    int m0 = blockIdx.y * TM;
    int n0 = blockIdx.x * TN;
    int wid = tid >> 5, lane = tid & 31;
    int wm = (wid & 3) * 32;
    int wn = (wid >> 2) * 64;
    int gid = lane >> 2, tig = lane & 3;

    float acc[2][8][4];
#pragma unroll
    for (int mt = 0; mt < 2; mt++)
#pragma unroll
        for (int nt = 0; nt < 8; nt++)
#pragma unroll
            for (int c = 0; c < 4; c++) acc[mt][nt][c] = 0.f;

    int am[4], ak[4], bk[4], bn[4];
#pragma unroll
    for (int r = 0; r < 4; r++) {
        int f = tid + 256 * r;
        am[r] = f >> 3;  ak[r] = (f & 7) * 4;
        bk[r] = f >> 5;  bn[r] = (f & 31) * 4;
    }

#define LOAD_STAGE(s, k0)                                                     \
    {                                                                         \
        _Pragma("unroll")                                                     \
        for (int r = 0; r < 4; r++) {                                         \
            cp_async16(as_u + (((s)*TM + am[r]) * AS_LD + ak[r]) * 4,         \
                       &A[(size_t)(m0 + am[r]) * K + (k0) + ak[r]]);          \
            cp_async16(bs_u + (((s)*TK + bk[r]) * BS_LD + bn[r]) * 4,         \
                       &W[(size_t)((k0) + bk[r]) * N + n0 + bn[r]]);          \
        }                                                                     \
        cp_commit();                                                          \
    }

    LOAD_STAGE(0, 0);

    const int NIT = K / TK;   // 32
    for (int it = 0; it < NIT; it++) {
        if (it + 1 < NIT) {
            LOAD_STAGE((it + 1) & 1, (it + 1) * TK);
            cp_wait<1>();
        } else {
            cp_wait<0>();
        }
        __syncthreads();

        int buf = it & 1;
        const float* Ab = As + buf * AS_STAGE;
        const float* Bb = Bs + buf * BS_STAGE;
#pragma unroll
        for (int ks = 0; ks < 4; ks++) {
            int kb = ks * 8;
            uint32_t af[2][4];
#pragma unroll
            for (int mt = 0; mt < 2; mt++) {
                int rm = wm + mt * 16 + gid;
                af[mt][0] = tf32_bits(Ab[rm * AS_LD + kb + tig]);
                af[mt][1] = tf32_bits(Ab[(rm + 8) * AS_LD + kb + tig]);
                af[mt][2] = tf32_bits(Ab[rm * AS_LD + kb + tig + 4]);
                af[mt][3] = tf32_bits(Ab[(rm + 8) * AS_LD + kb + tig + 4]);
            }
            uint32_t bf[8][2];
#pragma unroll
            for (int nt = 0; nt < 8; nt++) {
                int cn = wn + nt * 8 + gid;
                bf[nt][0] = tf32_bits(Bb[(kb + tig) * BS_LD + cn]);
                bf[nt][1] = tf32_bits(Bb[(kb + tig + 4) * BS_LD + cn]);
            }
#pragma unroll
            for (int mt = 0; mt < 2; mt++)
#pragma unroll
                for (int nt = 0; nt < 8; nt++) {
                    asm volatile(
                        "mma.sync.aligned.m16n8k8.row.col.f32.tf32.tf32.f32 "
                        "{%0,%1,%2,%3}, {%4,%5,%6,%7}, {%8,%9}, {%0,%1,%2,%3};"
                        : "+f"(acc[mt][nt][0]), "+f"(acc[mt][nt][1]),
                          "+f"(acc[mt][nt][2]), "+f"(acc[mt][nt][3])
                        : "r"(af[mt][0]), "r"(af[mt][1]),
                          "r"(af[mt][2]), "r"(af[mt][3]),
                          "r"(bf[nt][0]), "r"(bf[nt][1]));
                }
        }
        __syncthreads();
    }

#pragma unroll
    for (int mt = 0; mt < 2; mt++) {
        int row0 = m0 + wm + mt * 16 + gid;
#pragma unroll
        for (int nt = 0; nt < 8; nt++) {
            int col = n0 + wn + nt * 8 + 2 * tig;
            float bx = bias[col], by = bias[col + 1];
            float2 v0 = make_float2(acc[mt][nt][0] + bx, acc[mt][nt][1] + by);
            float2 v1 = make_float2(acc[mt][nt][2] + bx, acc[mt][nt][3] + by);
            *(float2*)&g_q[(size_t)row0 * N + col] = v0;
            *(float2*)&g_q[(size_t)(row0 + 8) * N + col] = v1;
        }
    }
}

// ---------------------------------------------------------------------------
// Tiled dots: block = 24 nodes (+8 halo rows). nsq + dots[d=1..8].
// ---------------------------------------------------------------------------
#define DT 24
#define DROWS 32
#define DOTS_SMEM (DROWS * HH * sizeof(float))

__global__ __launch_bounds__(256) void dots_tiled_kernel(const float* __restrict__ src)
{
    extern __shared__ float sh[];  // DROWS * HH
    int tid = threadIdx.x;
    int b = blockIdx.y;
    int i0 = blockIdx.x * DT;

#pragma unroll
    for (int r = 0; r < DROWS; r++) {
        int i = i0 + r;
        if (i < SS)
            ((float4*)(sh + (size_t)r * HH))[tid] =
                ((const float4*)(src + ((size_t)b * SS + i) * HH))[tid];
    }
    __syncthreads();

    int w = tid >> 5, lane = tid & 31;
#pragma unroll
    for (int nn = 0; nn < 3; nn++) {
        int ln = w * 3 + nn;          // 0..23
        int i = i0 + ln;
        if (i >= SS) continue;
        const float4* arow = (const float4*)(sh + (size_t)ln * HH);
        float4 a[8];
#pragma unroll
        for (int r = 0; r < 8; r++) a[r] = arow[lane + 32 * r];

#pragma unroll
        for (int d = 0; d <= RAD; d++) {
            if (d > 0 && i + d >= SS) break;
            float sum = 0.f;
            if (d == 0) {
#pragma unroll
                for (int r = 0; r < 8; r++)
                    sum += a[r].x*a[r].x + a[r].y*a[r].y + a[r].z*a[r].z + a[r].w*a[r].w;
            } else {
                const float4* crow = (const float4*)(sh + (size_t)(ln + d) * HH);
#pragma unroll
                for (int r = 0; r < 8; r++) {
                    float4 c = crow[lane + 32 * r];
                    sum += a[r].x*c.x + a[r].y*c.y + a[r].z*c.z + a[r].w*c.w;
                }
            }
#pragma unroll
            for (int o = 16; o > 0; o >>= 1)
                sum += __shfl_xor_sync(0xffffffffu, sum, o);
            if (lane == 0) {
                if (d == 0) g_nsq[b * SS + i] = sum;
                else g_dots[((size_t)b * RAD + (d - 1)) * SS + i] = sum;
            }
        }
    }
}

// ---------------------------------------------------------------------------
// mu: 8 threads/edge, conflict-free strided channels, A&S fast gelu.
// ---------------------------------------------------------------------------
__global__ __launch_bounds__(256) void mu_kernel6(
    const float* __restrict__ W1, const float* __restrict__ b1,
    const float* __restrict__ W2, const float* __restrict__ b2)
{
    __shared__ float w1a[INNERD], w1b[INNERD], bb1[INNERD], w2s[INNERD];
    int tid = threadIdx.x;
#pragma unroll
    for (int r = 0; r < 2; r++) {
        int k = tid + 256 * r;
        w1a[k] = W1[k];
        w1b[k] = W1[INNERD + k];
        bb1[k] = b1[k];
        w2s[k] = W2[k];
    }
    __syncthreads();

    int e = blockIdx.x * 32 + (tid >> 3);     // edge id
    int sub = tid & 7;
    int b = e >> 14;
    int r = e & 16383;
    int d = (r >> 11) + 1;
    int i = r & 2047;
    size_t slot = ((size_t)b * RAD + (d - 1)) * SS + i;
    bool valid = (i + d < SS);

    int j = valid ? (i + d) : i;
    float nsqi = g_nsq[b * SS + i];
    float nsqj = g_nsq[b * SS + j];
    float dot  = valid ? g_dots[slot] : 0.f;
    float dist = sqrtf(fmaxf(nsqi + nsqj - 2.f * dot, 0.f));
    float ni = fmaxf(sqrtf(nsqi), 1e-6f);
    float nj = fmaxf(sqrtf(nsqj), 1e-6f);
    float cosv = dot / (ni * nj);

    float z = 0.f;
#pragma unroll
    for (int m = 0; m < INNERD / 32; m++) {     // 16 iters
        int k = sub * 4 + m * 32;               // conflict-free across sub
        float4 wa = *(const float4*)&w1a[k];
        float4 wb = *(const float4*)&w1b[k];
        float4 bv = *(const float4*)&bb1[k];
        float4 w2v = *(const float4*)&w2s[k];
        float x0 = fmaf(dist, wa.x, fmaf(cosv, wb.x, bv.x));
        float x1 = fmaf(dist, wa.y, fmaf(cosv, wb.y, bv.y));
        float x2 = fmaf(dist, wa.z, fmaf(cosv, wb.z, bv.z));
        float x3 = fmaf(dist, wa.w, fmaf(cosv, wb.w, bv.w));
        z = fmaf(gelu_fast(x0), w2v.x, z);
        z = fmaf(gelu_fast(x1), w2v.y, z);
        z = fmaf(gelu_fast(x2), w2v.z, z);
        z = fmaf(gelu_fast(x3), w2v.w, z);
    }
    z += __shfl_xor_sync(0xffffffffu, z, 1);
    z += __shfl_xor_sync(0xffffffffu, z, 2);
    z += __shfl_xor_sync(0xffffffffu, z, 4);
    if (sub == 0) {
        if (!valid) { g_mu[slot] = 0.f; return; }
        float zz = z + b2[0];
        float sp = fmaxf(zz, 0.f) + log1pf(expf(-fabsf(zz)));
        g_mu[slot] = fminf(sp + 1e-5f, MU_MAXV);
    }
}

// ---------------------------------------------------------------------------
// Fused deg+lap+update+smooth, register-rolling tmp.
// LT=32 output rows, 50 state rows in smem; 512 threads, float2 per thread.
// ---------------------------------------------------------------------------
#define LT 32
#define LSROWS (LT + 18)     // 50
#define LTROWS (LT + 2)      // 34
#define LAPS_SMEM (((size_t)LSROWS * HH + LTROWS * 16 + LTROWS + LSROWS) * sizeof(float))

__global__ __launch_bounds__(512) void lapsmooth_kernel(
    const float* __restrict__ src, float* __restrict__ dst, float eta)
{
    extern __shared__ float sh[];
    float* st   = sh;                         // LSROWS * HH
    float* cof  = st + (size_t)LSROWS * HH;   // LTROWS * 16
    float* csm  = cof + LTROWS * 16;          // LTROWS
    float* isqs = csm + LTROWS;               // LSROWS

    int tid = threadIdx.x;
    int b = blockIdx.y;
    int i0 = blockIdx.x * LT;
    int c2 = tid * 2;

    // load state rows [i0-9, i0+41)
#pragma unroll
    for (int r = 0; r < LSROWS; r++) {
        int j = i0 - 9 + r;
        if (j >= 0 && j < SS)
            *(float2*)&st[(size_t)r * HH + c2] =
                *(const float2*)&src[((size_t)b * SS + j) * HH + c2];
    }
    // fused deg: isq for nodes [i0-9, i0+41)
    if (tid < LSROWS) {
        int n = i0 - 9 + tid;
        float isq = 0.f;
        if (n >= 0 && n < SS) {
            float deg = 0.f;
#pragma unroll
            for (int d = 1; d <= RAD; d++) {
                if (n + d < SS) deg += g_mu[((size_t)b * RAD + (d - 1)) * SS + n];
                if (n >= d)     deg += g_mu[((size_t)b * RAD + (d - 1)) * SS + n - d];
            }
            isq = rsqrtf(fmaxf(deg, 1e-6f));
        }
        isqs[tid] = isq;
    }
    __syncthreads();

    // coefficients for LTROWS tmp rows (clamped je)
    for (int idx = tid; idx < LTROWS * 16; idx += 512) {
        int jl = idx >> 4;
        int k = idx & 15;
        int j = i0 - 1 + jl;
        int je = min(max(j, 0), SS - 1);
        int d = (k >> 1) + 1;
        float c = 0.f;
        if (!(k & 1)) {
            int jn = je + d;
            if (jn < SS)
                c = g_mu[((size_t)b * RAD + (d - 1)) * SS + je] *
                    isqs[je - (i0 - 9)] * isqs[jn - (i0 - 9)];
        } else {
            int jn = je - d;
            if (jn >= 0)
                c = g_mu[((size_t)b * RAD + (d - 1)) * SS + jn] *
                    isqs[je - (i0 - 9)] * isqs[jn - (i0 - 9)];
        }
        cof[idx] = c;
    }
    __syncthreads();
    if (tid < LTROWS) {
        float s = 0.f;
#pragma unroll
        for (int k = 0; k < 16; k++) s += cof[tid * 16 + k];
        csm[tid] = s;
    }
    __syncthreads();

    float2 t0, t1, t2;
#pragma unroll
    for (int jl = 0; jl < LTROWS; jl++) {
        int j = i0 - 1 + jl;
        int je = min(max(j, 0), SS - 1);
        int jloc = je - i0 + 9;
        float2 si = *(const float2*)&st[(size_t)jloc * HH + c2];
        float cs = csm[jl];
        float2 acc;
        acc.x = cs * si.x; acc.y = cs * si.y;
#pragma unroll
        for (int k = 0; k < 16; k++) {
            float c = cof[jl * 16 + k];
            if (c != 0.f) {
                int d = (k >> 1) + 1;
                int off = (k & 1) ? -d : d;
                float2 sj = *(const float2*)&st[(size_t)(jloc + off) * HH + c2];
                acc.x = fmaf(-c, sj.x, acc.x);
                acc.y = fmaf(-c, sj.y, acc.y);
            }
        }
        float2 qv = *(const float2*)&g_q[((size_t)b * SS + je) * HH + c2];
        float2 tv;
        tv.x = si.x - eta * (acc.x - qv.x);
        tv.y = si.y - eta * (acc.y - qv.y);
        t0 = t1; t1 = t2; t2 = tv;
        if (jl >= 2) {
            int i = i0 + jl - 2;
            float2 o;
            o.x = t1.x - LAMv * (2.f * t1.x - t0.x - t2.x);
            o.y = t1.y - LAMv * (2.f * t1.y - t0.y - t2.y);
            *(float2*)&dst[((size_t)b * SS + i) * HH + c2] = o;
        }
    }
}

// ---------------------------------------------------------------------------
// Zero energy slots (out[BSH .. BSH+BB))
// ---------------------------------------------------------------------------
__global__ void zero_energy_kernel(float* __restrict__ out)
{
    if (threadIdx.x < BB) out[(size_t)BSH + threadIdx.x] = 0.f;
}

// ---------------------------------------------------------------------------
// Fused final energy: per tile, energy += 0.5 * sum mu_e * ||s_i - s_j||^2.
// ---------------------------------------------------------------------------
__global__ __launch_bounds__(256) void energy_tiled_kernel(
    const float* __restrict__ src, float* __restrict__ out)
{
    extern __shared__ float sh[];  // DROWS * HH
    int tid = threadIdx.x;
    int b = blockIdx.y;
    int i0 = blockIdx.x * DT;

#pragma unroll
    for (int r = 0; r < DROWS; r++) {
        int i = i0 + r;
        if (i < SS)
            ((float4*)(sh + (size_t)r * HH))[tid] =
                ((const float4*)(src + ((size_t)b * SS + i) * HH))[tid];
    }
    __syncthreads();

    int w = tid >> 5, lane = tid & 31;
    float wpart = 0.f;
#pragma unroll
    for (int nn = 0; nn < 3; nn++) {
        int ln = w * 3 + nn;
        int i = i0 + ln;
        if (i >= SS) continue;
        const float4* arow = (const float4*)(sh + (size_t)ln * HH);
        float4 a[8];
#pragma unroll
        for (int r = 0; r < 8; r++) a[r] = arow[lane + 32 * r];
#pragma unroll
        for (int d = 1; d <= RAD; d++) {
            if (i + d >= SS) break;
            const float4* crow = (const float4*)(sh + (size_t)(ln + d) * HH);
            float sum = 0.f;
#pragma unroll
            for (int r = 0; r < 8; r++) {
                float4 c = crow[lane + 32 * r];
                float dx = a[r].x - c.x, dy = a[r].y - c.y;
                float dz = a[r].z - c.z, dw = a[r].w - c.w;
                sum += dx*dx + dy*dy + dz*dz + dw*dw;
            }
#pragma unroll
            for (int o = 16; o > 0; o >>= 1)
                sum += __shfl_xor_sync(0xffffffffu, sum, o);
            if (lane == 0)
                wpart += g_mu[((size_t)b * RAD + (d - 1)) * SS + i] * sum;
        }
    }
    __shared__ float red[8];
    if (lane == 0) red[w] = wpart;
    __syncthreads();
    if (tid == 0) {
        float s = 0.f;
#pragma unroll
        for (int ww = 0; ww < 8; ww++) s += red[ww];
        atomicAdd(&out[(size_t)BSH + b], 0.5f * s);
    }
}

// ---------------------------------------------------------------------------
// out = layernorm(final + hidden) * gamma + beta
// ---------------------------------------------------------------------------
__global__ __launch_bounds__(256) void ln_kernel(
    const float* __restrict__ fin,
    const float* __restrict__ hidden,
    const float* __restrict__ gamma, const float* __restrict__ beta,
    float* __restrict__ out)
{
    int i = blockIdx.x, b = blockIdx.y;
    int tid = threadIdx.x;
    size_t base = ((size_t)b * SS + i) * HH + tid * 4;
    float4 s = *(const float4*)&fin[base];
    float4 h = *(const float4*)&hidden[base];
    float4 x;
    x.x = s.x + h.x; x.y = s.y + h.y; x.z = s.z + h.z; x.w = s.w + h.w;
    float sum = x.x + x.y + x.z + x.w;
    float sq  = x.x*x.x + x.y*x.y + x.z*x.z + x.w*x.w;
#pragma unroll
    for (int o = 16; o > 0; o >>= 1) {
        sum += __shfl_xor_sync(0xffffffffu, sum, o);
        sq  += __shfl_xor_sync(0xffffffffu, sq,  o);
    }
    __shared__ float rs[8], rq[8];
    int wid = tid >> 5, lane = tid & 31;
    if (lane == 0) { rs[wid] = sum; rq[wid] = sq; }
    __syncthreads();
    __shared__ float s_mean, s_rstd;
    if (tid == 0) {
        float ts = 0.f, tq = 0.f;
#pragma unroll
        for (int w = 0; w < 8; w++) { ts += rs[w]; tq += rq[w]; }
        float mean = ts / HH;
        float var = tq / HH - mean * mean;
        s_mean = mean;
        s_rstd = rsqrtf(var + 1e-5f);
    }
    __syncthreads();
    float mean = s_mean, rstd = s_rstd;
    int hbase = tid * 4;
    float4 o;
    o.x = (x.x - mean) * rstd * gamma[hbase+0] + beta[hbase+0];
    o.y = (x.y - mean) * rstd * gamma[hbase+1] + beta[hbase+1];
    o.z = (x.z - mean) * rstd * gamma[hbase+2] + beta[hbase+2];
    o.w = (x.w - mean) * rstd * gamma[hbase+3] + beta[hbase+3];
    *(float4*)&out[base] = o;
}

// ---------------------------------------------------------------------------
extern "C" void kernel_launch(void* const* d_in, const int* in_sizes, int n_in,
                              void* d_out, int out_size)
{
    const float* hidden = (const float*)d_in[0];
    const float* Wq = (const float*)d_in[3];
    const float* bq = (const float*)d_in[4];
    const float* W1 = (const float*)d_in[5];
    const float* b1 = (const float*)d_in[6];
    const float* W2 = (const float*)d_in[7];
    const float* b2 = (const float*)d_in[8];
    const float* gamma = (const float*)d_in[9];
    const float* beta  = (const float*)d_in[10];
    float* out = (float*)d_out;

    float *pA = nullptr, *pB = nullptr;
    cudaGetSymbolAddress((void**)&pA, g_stateA);
    cudaGetSymbolAddress((void**)&pB, g_stateB);

    cudaFuncSetAttribute(gemm_tf32_kernel,
                         cudaFuncAttributeMaxDynamicSharedMemorySize, GEMM_SMEM);
    cudaFuncSetAttribute(dots_tiled_kernel,
                         cudaFuncAttributeMaxDynamicSharedMemorySize, DOTS_SMEM);
    cudaFuncSetAttribute(energy_tiled_kernel,
                         cudaFuncAttributeMaxDynamicSharedMemorySize, DOTS_SMEM);
    cudaFuncSetAttribute(lapsmooth_kernel,
                         cudaFuncAttributeMaxDynamicSharedMemorySize, LAPS_SMEM);

    gemm_tf32_kernel<<<dim3(HH / TN, (BB * SS) / TM), 256, GEMM_SMEM>>>(hidden, Wq, bq);
    zero_energy_kernel<<<1, 32>>>(out);

    // ping-pong: hidden -> A -> B -> A -> B
    const float* srcs[KSTEPS + 1] = { hidden, pA, pB, pA, pB };
    float*       dsts[KSTEPS]     = { pA, pB, pA, pB };

    const int dots_grid = (SS + DT - 1) / DT;   // 86
    float eta = 0.1f;
    for (int step = 0; step < KSTEPS; step++) {
        dots_tiled_kernel<<<dim3(dots_grid, BB), 256, DOTS_SMEM>>>(srcs[step]);
        mu_kernel6<<<(BB * RAD * SS) / 32, 256>>>(W1, b1, W2, b2);
        lapsmooth_kernel<<<dim3(SS / LT, BB), 512, LAPS_SMEM>>>(srcs[step], dsts[step], eta);
        eta *= 0.9f;
    }
    energy_tiled_kernel<<<dim3(dots_grid, BB), 256, DOTS_SMEM>>>(srcs[KSTEPS], out);
    ln_kernel<<<dim3(SS, BB), 256>>>(srcs[KSTEPS], hidden, gamma, beta, out);
}

// round 10
// speedup vs baseline: 2.0120x; 1.1838x over previous
#include <cuda_runtime.h>
#include <math.h>
#include <stdint.h>

#define BB 4
#define SS 2048
#define HH 1024
#define INNERD 512
#define RAD 8
#define KSTEPS 4
#define LAMv 0.1f
#define MU_MAXV 10.0f

#define BSH (BB*SS*HH)

// mu lookup table: z(dist, cos), pre-softplus.
#define TABD 256
#define TABC 64
#define TAB_HD 0.5f
#define TAB_HC (2.0f / (TABC - 1))

// Scratch (no cudaMalloc allowed). Ping-pong state buffers.
__device__ float g_q[BSH];
__device__ float g_stateA[BSH];
__device__ float g_stateB[BSH];
__device__ float g_nsq[BB*SS];
__device__ float g_dots[BB*RAD*SS];
__device__ float g_mu[BB*RAD*SS];
__device__ float g_ztab[TABD * TABC];

__device__ __forceinline__ float to_tf32(float x) {
    float r;
    asm("cvt.rna.tf32.f32 %0, %1;" : "=f"(r) : "f"(x));
    return r;
}
__device__ __forceinline__ uint32_t tf32_bits(float x) {
    return __float_as_uint(to_tf32(x));
}
__device__ __forceinline__ void cp_async16(uint32_t s, const void* g) {
    asm volatile("cp.async.ca.shared.global [%0], [%1], 16;" :: "r"(s), "l"(g));
}
__device__ __forceinline__ void cp_commit() {
    asm volatile("cp.async.commit_group;");
}
template<int N>
__device__ __forceinline__ void cp_wait() {
    asm volatile("cp.async.wait_group %0;" :: "n"(N));
}

// ---------------------------------------------------------------------------
// GEMM (TF32 mma.sync, cp.async double-buffered): q = hidden @ Wq + bq.
// ---------------------------------------------------------------------------
#define TM 128
#define TN 128
#define TK 32
#define AS_LD (TK + 4)
#define BS_LD (TN + 4)
#define AS_STAGE (TM * AS_LD)
#define BS_STAGE (TK * BS_LD)
#define GEMM_SMEM ((2*AS_STAGE + 2*BS_STAGE) * sizeof(float))

__global__ __launch_bounds__(256) void gemm_tf32_kernel(
    const float* __restrict__ A,
    const float* __restrict__ W,
    const float* __restrict__ bias)
{
    extern __shared__ float sm[];
    float* As = sm;
    float* Bs = sm + 2 * AS_STAGE;
    uint32_t as_u = (uint32_t)__cvta_generic_to_shared(As);
    uint32_t bs_u = (uint32_t)__cvta_generic_to_shared(Bs);

    const int N = HH, K = HH;
    int tid = threadIdx.x;
    int m0 = blockIdx.y * TM;
    int n0 = blockIdx.x * TN;
    int wid = tid >> 5, lane = tid & 31;
    int wm = (wid & 3) * 32;
    int wn = (wid >> 2) * 64;
    int gid = lane >> 2, tig = lane & 3;

    float acc[2][8][4];
#pragma unroll
    for (int mt = 0; mt < 2; mt++)
#pragma unroll
        for (int nt = 0; nt < 8; nt++)
#pragma unroll
            for (int c = 0; c < 4; c++) acc[mt][nt][c] = 0.f;

    int am[4], ak[4], bk[4], bn[4];
#pragma unroll
    for (int r = 0; r < 4; r++) {
        int f = tid + 256 * r;
        am[r] = f >> 3;  ak[r] = (f & 7) * 4;
        bk[r] = f >> 5;  bn[r] = (f & 31) * 4;
    }

#define LOAD_STAGE(s, k0)                                                     \
    {                                                                         \
        _Pragma("unroll")                                                     \
        for (int r = 0; r < 4; r++) {                                         \
            cp_async16(as_u + (((s)*TM + am[r]) * AS_LD + ak[r]) * 4,         \
                       &A[(size_t)(m0 + am[r]) * K + (k0) + ak[r]]);          \
            cp_async16(bs_u + (((s)*TK + bk[r]) * BS_LD + bn[r]) * 4,         \
                       &W[(size_t)((k0) + bk[r]) * N + n0 + bn[r]]);          \
        }                                                                     \
        cp_commit();                                                          \
    }

    LOAD_STAGE(0, 0);

    const int NIT = K / TK;   // 32
    for (int it = 0; it < NIT; it++) {
        if (it + 1 < NIT) {
            LOAD_STAGE((it + 1) & 1, (it + 1) * TK);
            cp_wait<1>();
        } else {
            cp_wait<0>();
        }
        __syncthreads();

        int buf = it & 1;
        const float* Ab = As + buf * AS_STAGE;
        const float* Bb = Bs + buf * BS_STAGE;
#pragma unroll
        for (int ks = 0; ks < 4; ks++) {
            int kb = ks * 8;
            uint32_t af[2][4];
#pragma unroll
            for (int mt = 0; mt < 2; mt++) {
                int rm = wm + mt * 16 + gid;
                af[mt][0] = tf32_bits(Ab[rm * AS_LD + kb + tig]);
                af[mt][1] = tf32_bits(Ab[(rm + 8) * AS_LD + kb + tig]);
                af[mt][2] = tf32_bits(Ab[rm * AS_LD + kb + tig + 4]);
                af[mt][3] = tf32_bits(Ab[(rm + 8) * AS_LD + kb + tig + 4]);
            }
            uint32_t bf[8][2];
#pragma unroll
            for (int nt = 0; nt < 8; nt++) {
                int cn = wn + nt * 8 + gid;
                bf[nt][0] = tf32_bits(Bb[(kb + tig) * BS_LD + cn]);
                bf[nt][1] = tf32_bits(Bb[(kb + tig + 4) * BS_LD + cn]);
            }
#pragma unroll
            for (int mt = 0; mt < 2; mt++)
#pragma unroll
                for (int nt = 0; nt < 8; nt++) {
                    asm volatile(
                        "mma.sync.aligned.m16n8k8.row.col.f32.tf32.tf32.f32 "
                        "{%0,%1,%2,%3}, {%4,%5,%6,%7}, {%8,%9}, {%0,%1,%2,%3};"
                        : "+f"(acc[mt][nt][0]), "+f"(acc[mt][nt][1]),
                          "+f"(acc[mt][nt][2]), "+f"(acc[mt][nt][3])
                        : "r"(af[mt][0]), "r"(af[mt][1]),
                          "r"(af[mt][2]), "r"(af[mt][3]),
                          "r"(bf[nt][0]), "r"(bf[nt][1]));
                }
        }
        __syncthreads();
    }

#pragma unroll
    for (int mt = 0; mt < 2; mt++) {
        int row0 = m0 + wm + mt * 16 + gid;
#pragma unroll
        for (int nt = 0; nt < 8; nt++) {
            int col = n0 + wn + nt * 8 + 2 * tig;
            float bx = bias[col], by = bias[col + 1];
            float2 v0 = make_float2(acc[mt][nt][0] + bx, acc[mt][nt][1] + by);
            float2 v1 = make_float2(acc[mt][nt][2] + bx, acc[mt][nt][3] + by);
            *(float2*)&g_q[(size_t)row0 * N + col] = v0;
            *(float2*)&g_q[(size_t)(row0 + 8) * N + col] = v1;
        }
    }
}

// ---------------------------------------------------------------------------
// Build z-table: z(D, c) = sum_k gelu(D*W1a[k] + c*W1b[k] + b1[k]) * W2[k] + b2.
// One warp per entry, exact erff (runs once, ~8M gelu). Also zeroes energy.
// ---------------------------------------------------------------------------
__global__ __launch_bounds__(256) void build_tab_kernel(
    const float* __restrict__ W1, const float* __restrict__ b1,
    const float* __restrict__ W2, const float* __restrict__ b2,
    float* __restrict__ out)
{
    if (blockIdx.x == 0 && threadIdx.x < BB)
        out[(size_t)BSH + threadIdx.x] = 0.f;   // zero energy slots

    int w = (blockIdx.x * 256 + threadIdx.x) >> 5;   // entry id
    int lane = threadIdx.x & 31;
    if (w >= TABD * TABC) return;
    float D = (float)(w / TABC) * TAB_HD;
    float c = -1.f + (float)(w % TABC) * TAB_HC;

    const float IS2 = 0.70710678118654752f;
    float z = 0.f;
#pragma unroll 4
    for (int k = lane; k < INNERD; k += 32) {
        float x = fmaf(D, W1[k], fmaf(c, W1[INNERD + k], b1[k]));
        float g = 0.5f * x * (1.f + erff(x * IS2));
        z = fmaf(g, W2[k], z);
    }
#pragma unroll
    for (int o = 16; o > 0; o >>= 1)
        z += __shfl_xor_sync(0xffffffffu, z, o);
    if (lane == 0) g_ztab[w] = z + b2[0];
}

// ---------------------------------------------------------------------------
// Tiled dots: block = 24 nodes (+8 halo rows). nsq + dots[d=1..8].
// ---------------------------------------------------------------------------
#define DT 24
#define DROWS 32
#define DOTS_SMEM (DROWS * HH * sizeof(float))

__global__ __launch_bounds__(256) void dots_tiled_kernel(const float* __restrict__ src)
{
    extern __shared__ float sh[];  // DROWS * HH
    int tid = threadIdx.x;
    int b = blockIdx.y;
    int i0 = blockIdx.x * DT;

#pragma unroll
    for (int r = 0; r < DROWS; r++) {
        int i = i0 + r;
        if (i < SS)
            ((float4*)(sh + (size_t)r * HH))[tid] =
                ((const float4*)(src + ((size_t)b * SS + i) * HH))[tid];
    }
    __syncthreads();

    int w = tid >> 5, lane = tid & 31;
#pragma unroll
    for (int nn = 0; nn < 3; nn++) {
        int ln = w * 3 + nn;          // 0..23
        int i = i0 + ln;
        if (i >= SS) continue;
        const float4* arow = (const float4*)(sh + (size_t)ln * HH);
        float4 a[8];
#pragma unroll
        for (int r = 0; r < 8; r++) a[r] = arow[lane + 32 * r];

#pragma unroll
        for (int d = 0; d <= RAD; d++) {
            if (d > 0 && i + d >= SS) break;
            float sum = 0.f;
            if (d == 0) {
#pragma unroll
                for (int r = 0; r < 8; r++)
                    sum += a[r].x*a[r].x + a[r].y*a[r].y + a[r].z*a[r].z + a[r].w*a[r].w;
            } else {
                const float4* crow = (const float4*)(sh + (size_t)(ln + d) * HH);
#pragma unroll
                for (int r = 0; r < 8; r++) {
                    float4 c = crow[lane + 32 * r];
                    sum += a[r].x*c.x + a[r].y*c.y + a[r].z*c.z + a[r].w*c.w;
                }
            }
#pragma unroll
            for (int o = 16; o > 0; o >>= 1)
                sum += __shfl_xor_sync(0xffffffffu, sum, o);
            if (lane == 0) {
                if (d == 0) g_nsq[b * SS + i] = sum;
                else g_dots[((size_t)b * RAD + (d - 1)) * SS + i] = sum;
            }
        }
    }
}

// ---------------------------------------------------------------------------
// mu via table lookup: 1 thread per edge, bilinear interp of z, then
// softplus + clamp. Table is 64 KB -> L1/L2 resident.
// ---------------------------------------------------------------------------
__global__ __launch_bounds__(256) void mu_lookup_kernel()
{
    int e = blockIdx.x * 256 + threadIdx.x;   // < BB*RAD*SS
    int b = e >> 14;
    int r = e & 16383;
    int d = (r >> 11) + 1;
    int i = r & 2047;
    size_t slot = ((size_t)b * RAD + (d - 1)) * SS + i;
    if (i + d >= SS) { g_mu[slot] = 0.f; return; }

    float nsqi = g_nsq[b * SS + i];
    float nsqj = g_nsq[b * SS + i + d];
    float dot  = g_dots[slot];
    float dist = sqrtf(fmaxf(nsqi + nsqj - 2.f * dot, 0.f));
    float ni = fmaxf(sqrtf(nsqi), 1e-6f);
    float nj = fmaxf(sqrtf(nsqj), 1e-6f);
    float cosv = dot / (ni * nj);

    // bilinear lookup
    float Df = dist * (1.f / TAB_HD);
    int di = (int)Df;
    di = min(max(di, 0), TABD - 2);
    float fd = fminf(fmaxf(Df - (float)di, 0.f), 1.f);

    float Cf = (cosv + 1.f) * (1.f / TAB_HC);
    int cj = (int)Cf;
    cj = min(max(cj, 0), TABC - 2);
    float fc = fminf(fmaxf(Cf - (float)cj, 0.f), 1.f);

    const float* t0 = &g_ztab[di * TABC + cj];
    float z00 = t0[0],        z01 = t0[1];
    float z10 = t0[TABC],     z11 = t0[TABC + 1];
    float zl = z00 + fc * (z01 - z00);
    float zh = z10 + fc * (z11 - z10);
    float z  = zl + fd * (zh - zl);

    float sp = fmaxf(z, 0.f) + log1pf(expf(-fabsf(z)));
    g_mu[slot] = fminf(sp + 1e-5f, MU_MAXV);
}

// ---------------------------------------------------------------------------
// Fused deg+lap+update+smooth, register-rolling tmp.
// LT=32 output rows, 50 state rows in smem; 512 threads, float2 per thread.
// ---------------------------------------------------------------------------
#define LT 32
#define LSROWS (LT + 18)     // 50
#define LTROWS (LT + 2)      // 34
#define LAPS_SMEM (((size_t)LSROWS * HH + LTROWS * 16 + LTROWS + LSROWS) * sizeof(float))

__global__ __launch_bounds__(512) void lapsmooth_kernel(
    const float* __restrict__ src, float* __restrict__ dst, float eta)
{
    extern __shared__ float sh[];
    float* st   = sh;                         // LSROWS * HH
    float* cof  = st + (size_t)LSROWS * HH;   // LTROWS * 16
    float* csm  = cof + LTROWS * 16;          // LTROWS
    float* isqs = csm + LTROWS;               // LSROWS

    int tid = threadIdx.x;
    int b = blockIdx.y;
    int i0 = blockIdx.x * LT;
    int c2 = tid * 2;

    // load state rows [i0-9, i0+41)
#pragma unroll
    for (int r = 0; r < LSROWS; r++) {
        int j = i0 - 9 + r;
        if (j >= 0 && j < SS)
            *(float2*)&st[(size_t)r * HH + c2] =
                *(const float2*)&src[((size_t)b * SS + j) * HH + c2];
    }
    // fused deg: isq for nodes [i0-9, i0+41)
    if (tid < LSROWS) {
        int n = i0 - 9 + tid;
        float isq = 0.f;
        if (n >= 0 && n < SS) {
            float deg = 0.f;
#pragma unroll
            for (int d = 1; d <= RAD; d++) {
                if (n + d < SS) deg += g_mu[((size_t)b * RAD + (d - 1)) * SS + n];
                if (n >= d)     deg += g_mu[((size_t)b * RAD + (d - 1)) * SS + n - d];
            }
            isq = rsqrtf(fmaxf(deg, 1e-6f));
        }
        isqs[tid] = isq;
    }
    __syncthreads();

    // coefficients for LTROWS tmp rows (clamped je)
    for (int idx = tid; idx < LTROWS * 16; idx += 512) {
        int jl = idx >> 4;
        int k = idx & 15;
        int j = i0 - 1 + jl;
        int je = min(max(j, 0), SS - 1);
        int d = (k >> 1) + 1;
        float c = 0.f;
        if (!(k & 1)) {
            int jn = je + d;
            if (jn < SS)
                c = g_mu[((size_t)b * RAD + (d - 1)) * SS + je] *
                    isqs[je - (i0 - 9)] * isqs[jn - (i0 - 9)];
        } else {
            int jn = je - d;
            if (jn >= 0)
                c = g_mu[((size_t)b * RAD + (d - 1)) * SS + jn] *
                    isqs[je - (i0 - 9)] * isqs[jn - (i0 - 9)];
        }
        cof[idx] = c;
    }
    __syncthreads();
    if (tid < LTROWS) {
        float s = 0.f;
#pragma unroll
        for (int k = 0; k < 16; k++) s += cof[tid * 16 + k];
        csm[tid] = s;
    }
    __syncthreads();

    float2 t0, t1, t2;
#pragma unroll
    for (int jl = 0; jl < LTROWS; jl++) {
        int j = i0 - 1 + jl;
        int je = min(max(j, 0), SS - 1);
        int jloc = je - i0 + 9;
        float2 si = *(const float2*)&st[(size_t)jloc * HH + c2];
        float cs = csm[jl];
        float2 acc;
        acc.x = cs * si.x; acc.y = cs * si.y;
#pragma unroll
        for (int k = 0; k < 16; k++) {
            float c = cof[jl * 16 + k];
            if (c != 0.f) {
                int d = (k >> 1) + 1;
                int off = (k & 1) ? -d : d;
                float2 sj = *(const float2*)&st[(size_t)(jloc + off) * HH + c2];
                acc.x = fmaf(-c, sj.x, acc.x);
                acc.y = fmaf(-c, sj.y, acc.y);
            }
        }
        float2 qv = *(const float2*)&g_q[((size_t)b * SS + je) * HH + c2];
        float2 tv;
        tv.x = si.x - eta * (acc.x - qv.x);
        tv.y = si.y - eta * (acc.y - qv.y);
        t0 = t1; t1 = t2; t2 = tv;
        if (jl >= 2) {
            int i = i0 + jl - 2;
            float2 o;
            o.x = t1.x - LAMv * (2.f * t1.x - t0.x - t2.x);
            o.y = t1.y - LAMv * (2.f * t1.y - t0.y - t2.y);
            *(float2*)&dst[((size_t)b * SS + i) * HH + c2] = o;
        }
    }
}

// ---------------------------------------------------------------------------
// Fused final energy: per tile, energy += 0.5 * sum mu_e * ||s_i - s_j||^2.
// ---------------------------------------------------------------------------
__global__ __launch_bounds__(256) void energy_tiled_kernel(
    const float* __restrict__ src, float* __restrict__ out)
{
    extern __shared__ float sh[];  // DROWS * HH
    int tid = threadIdx.x;
    int b = blockIdx.y;
    int i0 = blockIdx.x * DT;

#pragma unroll
    for (int r = 0; r < DROWS; r++) {
        int i = i0 + r;
        if (i < SS)
            ((float4*)(sh + (size_t)r * HH))[tid] =
                ((const float4*)(src + ((size_t)b * SS + i) * HH))[tid];
    }
    __syncthreads();

    int w = tid >> 5, lane = tid & 31;
    float wpart = 0.f;
#pragma unroll
    for (int nn = 0; nn < 3; nn++) {
        int ln = w * 3 + nn;
        int i = i0 + ln;
        if (i >= SS) continue;
        const float4* arow = (const float4*)(sh + (size_t)ln * HH);
        float4 a[8];
#pragma unroll
        for (int r = 0; r < 8; r++) a[r] = arow[lane + 32 * r];
#pragma unroll
        for (int d = 1; d <= RAD; d++) {
            if (i + d >= SS) break;
            const float4* crow = (const float4*)(sh + (size_t)(ln + d) * HH);
            float sum = 0.f;
#pragma unroll
            for (int r = 0; r < 8; r++) {
                float4 c = crow[lane + 32 * r];
                float dx = a[r].x - c.x, dy = a[r].y - c.y;
                float dz = a[r].z - c.z, dw = a[r].w - c.w;
                sum += dx*dx + dy*dy + dz*dz + dw*dw;
            }
#pragma unroll
            for (int o = 16; o > 0; o >>= 1)
                sum += __shfl_xor_sync(0xffffffffu, sum, o);
            if (lane == 0)
                wpart += g_mu[((size_t)b * RAD + (d - 1)) * SS + i] * sum;
        }
    }
    __shared__ float red[8];
    if (lane == 0) red[w] = wpart;
    __syncthreads();
    if (tid == 0) {
        float s = 0.f;
#pragma unroll
        for (int ww = 0; ww < 8; ww++) s += red[ww];
        atomicAdd(&out[(size_t)BSH + b], 0.5f * s);
    }
}

// ---------------------------------------------------------------------------
// out = layernorm(final + hidden) * gamma + beta
// ---------------------------------------------------------------------------
__global__ __launch_bounds__(256) void ln_kernel(
    const float* __restrict__ fin,
    const float* __restrict__ hidden,
    const float* __restrict__ gamma, const float* __restrict__ beta,
    float* __restrict__ out)
{
    int i = blockIdx.x, b = blockIdx.y;
    int tid = threadIdx.x;
    size_t base = ((size_t)b * SS + i) * HH + tid * 4;
    float4 s = *(const float4*)&fin[base];
    float4 h = *(const float4*)&hidden[base];
    float4 x;
    x.x = s.x + h.x; x.y = s.y + h.y; x.z = s.z + h.z; x.w = s.w + h.w;
    float sum = x.x + x.y + x.z + x.w;
    float sq  = x.x*x.x + x.y*x.y + x.z*x.z + x.w*x.w;
#pragma unroll
    for (int o = 16; o > 0; o >>= 1) {
        sum += __shfl_xor_sync(0xffffffffu, sum, o);
        sq  += __shfl_xor_sync(0xffffffffu, sq,  o);
    }
    __shared__ float rs[8], rq[8];
    int wid = tid >> 5, lane = tid & 31;
    if (lane == 0) { rs[wid] = sum; rq[wid] = sq; }
    __syncthreads();
    __shared__ float s_mean, s_rstd;
    if (tid == 0) {
        float ts = 0.f, tq = 0.f;
#pragma unroll
        for (int w = 0; w < 8; w++) { ts += rs[w]; tq += rq[w]; }
        float mean = ts / HH;
        float var = tq / HH - mean * mean;
        s_mean = mean;
        s_rstd = rsqrtf(var + 1e-5f);
    }
    __syncthreads();
    float mean = s_mean, rstd = s_rstd;
    int hbase = tid * 4;
    float4 o;
    o.x = (x.x - mean) * rstd * gamma[hbase+0] + beta[hbase+0];
    o.y = (x.y - mean) * rstd * gamma[hbase+1] + beta[hbase+1];
    o.z = (x.z - mean) * rstd * gamma[hbase+2] + beta[hbase+2];
    o.w = (x.w - mean) * rstd * gamma[hbase+3] + beta[hbase+3];
    *(float4*)&out[base] = o;
}

// ---------------------------------------------------------------------------
extern "C" void kernel_launch(void* const* d_in, const int* in_sizes, int n_in,
                              void* d_out, int out_size)
{
    const float* hidden = (const float*)d_in[0];
    const float* Wq = (const float*)d_in[3];
    const float* bq = (const float*)d_in[4];
    const float* W1 = (const float*)d_in[5];
    const float* b1 = (const float*)d_in[6];
    const float* W2 = (const float*)d_in[7];
    const float* b2 = (const float*)d_in[8];
    const float* gamma = (const float*)d_in[9];
    const float* beta  = (const float*)d_in[10];
    float* out = (float*)d_out;

    float *pA = nullptr, *pB = nullptr;
    cudaGetSymbolAddress((void**)&pA, g_stateA);
    cudaGetSymbolAddress((void**)&pB, g_stateB);

    cudaFuncSetAttribute(gemm_tf32_kernel,
                         cudaFuncAttributeMaxDynamicSharedMemorySize, GEMM_SMEM);
    cudaFuncSetAttribute(dots_tiled_kernel,
                         cudaFuncAttributeMaxDynamicSharedMemorySize, DOTS_SMEM);
    cudaFuncSetAttribute(energy_tiled_kernel,
                         cudaFuncAttributeMaxDynamicSharedMemorySize, DOTS_SMEM);
    cudaFuncSetAttribute(lapsmooth_kernel,
                         cudaFuncAttributeMaxDynamicSharedMemorySize, LAPS_SMEM);

    gemm_tf32_kernel<<<dim3(HH / TN, (BB * SS) / TM), 256, GEMM_SMEM>>>(hidden, Wq, bq);
    build_tab_kernel<<<(TABD * TABC * 32 + 255) / 256, 256>>>(W1, b1, W2, b2, out);

    // ping-pong: hidden -> A -> B -> A -> B
    const float* srcs[KSTEPS + 1] = { hidden, pA, pB, pA, pB };
    float*       dsts[KSTEPS]     = { pA, pB, pA, pB };

    const int dots_grid = (SS + DT - 1) / DT;   // 86
    float eta = 0.1f;
    for (int step = 0; step < KSTEPS; step++) {
        dots_tiled_kernel<<<dim3(dots_grid, BB), 256, DOTS_SMEM>>>(srcs[step]);
        mu_lookup_kernel<<<(BB * RAD * SS) / 256, 256>>>();
        lapsmooth_kernel<<<dim3(SS / LT, BB), 512, LAPS_SMEM>>>(srcs[step], dsts[step], eta);
        eta *= 0.9f;
    }
    energy_tiled_kernel<<<dim3(dots_grid, BB), 256, DOTS_SMEM>>>(srcs[KSTEPS], out);
    ln_kernel<<<dim3(SS, BB), 256>>>(srcs[KSTEPS], hidden, gamma, beta, out);
}

// round 11
// speedup vs baseline: 2.2007x; 1.0938x over previous
#include <cuda_runtime.h>
#include <math.h>
#include <stdint.h>

#define BB 4
#define SS 2048
#define HH 1024
#define INNERD 512
#define RAD 8
#define KSTEPS 4
#define LAMv 0.1f
#define MU_MAXV 10.0f

#define BSH (BB*SS*HH)

// mu lookup table: z(dist, cos), pre-softplus.
#define TABD 256
#define TABC 64
#define TAB_HD 0.5f
#define TAB_HC (2.0f / (TABC - 1))

// Scratch (no cudaMalloc allowed). Ping-pong state buffers.
__device__ float g_q[BSH];
__device__ float g_stateA[BSH];
__device__ float g_stateB[BSH];
__device__ float g_nsqH[2 * BB * SS];          // per-column-half partials
__device__ float g_dotsH[2 * BB * RAD * SS];   // per-column-half partials
__device__ float g_mu[BB*RAD*SS];
__device__ float g_ztab[TABD * TABC];

__device__ __forceinline__ float to_tf32(float x) {
    float r;
    asm("cvt.rna.tf32.f32 %0, %1;" : "=f"(r) : "f"(x));
    return r;
}
__device__ __forceinline__ uint32_t tf32_bits(float x) {
    return __float_as_uint(to_tf32(x));
}
__device__ __forceinline__ void cp_async16(uint32_t s, const void* g) {
    asm volatile("cp.async.ca.shared.global [%0], [%1], 16;" :: "r"(s), "l"(g));
}
__device__ __forceinline__ void cp_commit() {
    asm volatile("cp.async.commit_group;");
}
template<int N>
__device__ __forceinline__ void cp_wait() {
    asm volatile("cp.async.wait_group %0;" :: "n"(N));
}

// ---------------------------------------------------------------------------
// GEMM (TF32 mma.sync, cp.async double-buffered): q = hidden @ Wq + bq.
// ---------------------------------------------------------------------------
#define TM 128
#define TN 128
#define TK 32
#define AS_LD (TK + 4)
#define BS_LD (TN + 4)
#define AS_STAGE (TM * AS_LD)
#define BS_STAGE (TK * BS_LD)
#define GEMM_SMEM ((2*AS_STAGE + 2*BS_STAGE) * sizeof(float))

__global__ __launch_bounds__(256) void gemm_tf32_kernel(
    const float* __restrict__ A,
    const float* __restrict__ W,
    const float* __restrict__ bias)
{
    extern __shared__ float sm[];
    float* As = sm;
    float* Bs = sm + 2 * AS_STAGE;
    uint32_t as_u = (uint32_t)__cvta_generic_to_shared(As);
    uint32_t bs_u = (uint32_t)__cvta_generic_to_shared(Bs);

    const int N = HH, K = HH;
    int tid = threadIdx.x;
    int m0 = blockIdx.y * TM;
    int n0 = blockIdx.x * TN;
    int wid = tid >> 5, lane = tid & 31;
    int wm = (wid & 3) * 32;
    int wn = (wid >> 2) * 64;
    int gid = lane >> 2, tig = lane & 3;

    float acc[2][8][4];
#pragma unroll
    for (int mt = 0; mt < 2; mt++)
#pragma unroll
        for (int nt = 0; nt < 8; nt++)
#pragma unroll
            for (int c = 0; c < 4; c++) acc[mt][nt][c] = 0.f;

    int am[4], ak[4], bk[4], bn[4];
#pragma unroll
    for (int r = 0; r < 4; r++) {
        int f = tid + 256 * r;
        am[r] = f >> 3;  ak[r] = (f & 7) * 4;
        bk[r] = f >> 5;  bn[r] = (f & 31) * 4;
    }

#define LOAD_STAGE(s, k0)                                                     \
    {                                                                         \
        _Pragma("unroll")                                                     \
        for (int r = 0; r < 4; r++) {                                         \
            cp_async16(as_u + (((s)*TM + am[r]) * AS_LD + ak[r]) * 4,         \
                       &A[(size_t)(m0 + am[r]) * K + (k0) + ak[r]]);          \
            cp_async16(bs_u + (((s)*TK + bk[r]) * BS_LD + bn[r]) * 4,         \
                       &W[(size_t)((k0) + bk[r]) * N + n0 + bn[r]]);          \
        }                                                                     \
        cp_commit();                                                          \
    }

    LOAD_STAGE(0, 0);

    const int NIT = K / TK;   // 32
    for (int it = 0; it < NIT; it++) {
        if (it + 1 < NIT) {
            LOAD_STAGE((it + 1) & 1, (it + 1) * TK);
            cp_wait<1>();
        } else {
            cp_wait<0>();
        }
        __syncthreads();

        int buf = it & 1;
        const float* Ab = As + buf * AS_STAGE;
        const float* Bb = Bs + buf * BS_STAGE;
#pragma unroll
        for (int ks = 0; ks < 4; ks++) {
            int kb = ks * 8;
            uint32_t af[2][4];
#pragma unroll
            for (int mt = 0; mt < 2; mt++) {
                int rm = wm + mt * 16 + gid;
                af[mt][0] = tf32_bits(Ab[rm * AS_LD + kb + tig]);
                af[mt][1] = tf32_bits(Ab[(rm + 8) * AS_LD + kb + tig]);
                af[mt][2] = tf32_bits(Ab[rm * AS_LD + kb + tig + 4]);
                af[mt][3] = tf32_bits(Ab[(rm + 8) * AS_LD + kb + tig + 4]);
            }
            uint32_t bf[8][2];
#pragma unroll
            for (int nt = 0; nt < 8; nt++) {
                int cn = wn + nt * 8 + gid;
                bf[nt][0] = tf32_bits(Bb[(kb + tig) * BS_LD + cn]);
                bf[nt][1] = tf32_bits(Bb[(kb + tig + 4) * BS_LD + cn]);
            }
#pragma unroll
            for (int mt = 0; mt < 2; mt++)
#pragma unroll
                for (int nt = 0; nt < 8; nt++) {
                    asm volatile(
                        "mma.sync.aligned.m16n8k8.row.col.f32.tf32.tf32.f32 "
                        "{%0,%1,%2,%3}, {%4,%5,%6,%7}, {%8,%9}, {%0,%1,%2,%3};"
                        : "+f"(acc[mt][nt][0]), "+f"(acc[mt][nt][1]),
                          "+f"(acc[mt][nt][2]), "+f"(acc[mt][nt][3])
                        : "r"(af[mt][0]), "r"(af[mt][1]),
                          "r"(af[mt][2]), "r"(af[mt][3]),
                          "r"(bf[nt][0]), "r"(bf[nt][1]));
                }
        }
        __syncthreads();
    }

#pragma unroll
    for (int mt = 0; mt < 2; mt++) {
        int row0 = m0 + wm + mt * 16 + gid;
#pragma unroll
        for (int nt = 0; nt < 8; nt++) {
            int col = n0 + wn + nt * 8 + 2 * tig;
            float bx = bias[col], by = bias[col + 1];
            float2 v0 = make_float2(acc[mt][nt][0] + bx, acc[mt][nt][1] + by);
            float2 v1 = make_float2(acc[mt][nt][2] + bx, acc[mt][nt][3] + by);
            *(float2*)&g_q[(size_t)row0 * N + col] = v0;
            *(float2*)&g_q[(size_t)(row0 + 8) * N + col] = v1;
        }
    }
}

// ---------------------------------------------------------------------------
// Build z-table (runs once). Also zeroes energy slots.
// ---------------------------------------------------------------------------
__global__ __launch_bounds__(256) void build_tab_kernel(
    const float* __restrict__ W1, const float* __restrict__ b1,
    const float* __restrict__ W2, const float* __restrict__ b2,
    float* __restrict__ out)
{
    if (blockIdx.x == 0 && threadIdx.x < BB)
        out[(size_t)BSH + threadIdx.x] = 0.f;

    int w = (blockIdx.x * 256 + threadIdx.x) >> 5;
    int lane = threadIdx.x & 31;
    if (w >= TABD * TABC) return;
    float D = (float)(w / TABC) * TAB_HD;
    float c = -1.f + (float)(w % TABC) * TAB_HC;

    const float IS2 = 0.70710678118654752f;
    float z = 0.f;
#pragma unroll 4
    for (int k = lane; k < INNERD; k += 32) {
        float x = fmaf(D, W1[k], fmaf(c, W1[INNERD + k], b1[k]));
        float g = 0.5f * x * (1.f + erff(x * IS2));
        z = fmaf(g, W2[k], z);
    }
#pragma unroll
    for (int o = 16; o > 0; o >>= 1)
        z += __shfl_xor_sync(0xffffffffu, z, o);
    if (lane == 0) g_ztab[w] = z + b2[0];
}

// ---------------------------------------------------------------------------
// Tiled dots, COLUMN-HALVED: blockIdx.z = half (512 cols). Partial sums into
// g_nsqH / g_dotsH. Smem 64 KB -> 3 blocks/SM.
// ---------------------------------------------------------------------------
#define DT 24
#define DROWS 32
#define DHALF 512
#define DOTS_SMEM (DROWS * DHALF * sizeof(float))

__global__ __launch_bounds__(256) void dots_half_kernel(const float* __restrict__ src)
{
    extern __shared__ float sh[];  // DROWS * DHALF
    int tid = threadIdx.x;
    int b = blockIdx.y;
    int half = blockIdx.z;
    int i0 = blockIdx.x * DT;
    int cb = half * DHALF;

#pragma unroll
    for (int s = 0; s < (DROWS * DHALF / 4) / 256; s++) {   // 16 iters
        int slot = tid + 256 * s;
        int row = slot >> 7;            // / 128 float4 per row
        int c4 = slot & 127;
        int i = i0 + row;
        if (i < SS)
            ((float4*)(sh + (size_t)row * DHALF))[c4] =
                ((const float4*)(src + ((size_t)b * SS + i) * HH + cb))[c4];
    }
    __syncthreads();

    int w = tid >> 5, lane = tid & 31;
    size_t hn = (size_t)half * BB * SS;
    size_t hd = (size_t)half * BB * RAD * SS;
#pragma unroll
    for (int nn = 0; nn < 3; nn++) {
        int ln = w * 3 + nn;          // 0..23
        int i = i0 + ln;
        if (i >= SS) continue;
        const float4* arow = (const float4*)(sh + (size_t)ln * DHALF);
        float4 a[4];
#pragma unroll
        for (int r = 0; r < 4; r++) a[r] = arow[lane + 32 * r];

#pragma unroll
        for (int d = 0; d <= RAD; d++) {
            if (d > 0 && i + d >= SS) break;
            float sum = 0.f;
            if (d == 0) {
#pragma unroll
                for (int r = 0; r < 4; r++)
                    sum += a[r].x*a[r].x + a[r].y*a[r].y + a[r].z*a[r].z + a[r].w*a[r].w;
            } else {
                const float4* crow = (const float4*)(sh + (size_t)(ln + d) * DHALF);
#pragma unroll
                for (int r = 0; r < 4; r++) {
                    float4 c = crow[lane + 32 * r];
                    sum += a[r].x*c.x + a[r].y*c.y + a[r].z*c.z + a[r].w*c.w;
                }
            }
#pragma unroll
            for (int o = 16; o > 0; o >>= 1)
                sum += __shfl_xor_sync(0xffffffffu, sum, o);
            if (lane == 0) {
                if (d == 0) g_nsqH[hn + b * SS + i] = sum;
                else g_dotsH[hd + ((size_t)b * RAD + (d - 1)) * SS + i] = sum;
            }
        }
    }
}

// ---------------------------------------------------------------------------
// mu via table lookup (sums the two column-half partials).
// ---------------------------------------------------------------------------
__global__ __launch_bounds__(256) void mu_lookup_kernel()
{
    int e = blockIdx.x * 256 + threadIdx.x;   // < BB*RAD*SS
    int b = e >> 14;
    int r = e & 16383;
    int d = (r >> 11) + 1;
    int i = r & 2047;
    size_t slot = ((size_t)b * RAD + (d - 1)) * SS + i;
    if (i + d >= SS) { g_mu[slot] = 0.f; return; }

    float nsqi = g_nsqH[b * SS + i] + g_nsqH[(size_t)BB * SS + b * SS + i];
    float nsqj = g_nsqH[b * SS + i + d] + g_nsqH[(size_t)BB * SS + b * SS + i + d];
    float dot  = g_dotsH[slot] + g_dotsH[(size_t)BB * RAD * SS + slot];
    float dist = sqrtf(fmaxf(nsqi + nsqj - 2.f * dot, 0.f));
    float ni = fmaxf(sqrtf(nsqi), 1e-6f);
    float nj = fmaxf(sqrtf(nsqj), 1e-6f);
    float cosv = dot / (ni * nj);

    float Df = dist * (1.f / TAB_HD);
    int di = (int)Df;
    di = min(max(di, 0), TABD - 2);
    float fd = fminf(fmaxf(Df - (float)di, 0.f), 1.f);

    float Cf = (cosv + 1.f) * (1.f / TAB_HC);
    int cj = (int)Cf;
    cj = min(max(cj, 0), TABC - 2);
    float fc = fminf(fmaxf(Cf - (float)cj, 0.f), 1.f);

    const float* t0 = &g_ztab[di * TABC + cj];
    float z00 = t0[0],        z01 = t0[1];
    float z10 = t0[TABC],     z11 = t0[TABC + 1];
    float zl = z00 + fc * (z01 - z00);
    float zh = z10 + fc * (z11 - z10);
    float z  = zl + fd * (zh - zl);

    float sp = fmaxf(z, 0.f) + log1pf(expf(-fabsf(z)));
    g_mu[slot] = fminf(sp + 1e-5f, MU_MAXV);
}

// ---------------------------------------------------------------------------
// Fused deg+lap+update+smooth, COLUMN-TILED: 32 rows x 256 cols per block.
// Smem ~54 KB -> 4 blocks/SM. grid (SS/LT, HH/LCW, BB), 128 threads.
// ---------------------------------------------------------------------------
#define LT 32
#define LCW 256
#define LSROWS (LT + 18)     // 50
#define LTROWS (LT + 2)      // 34
#define LAPS_SMEM (((size_t)LSROWS * LCW + LTROWS * 16 + LTROWS + LSROWS) * sizeof(float))

__global__ __launch_bounds__(128) void lapsmooth_kernel(
    const float* __restrict__ src, float* __restrict__ dst, float eta)
{
    extern __shared__ float sh[];
    float* st   = sh;                          // LSROWS * LCW
    float* cof  = st + (size_t)LSROWS * LCW;   // LTROWS * 16
    float* csm  = cof + LTROWS * 16;           // LTROWS
    float* isqs = csm + LTROWS;                // LSROWS

    int tid = threadIdx.x;
    int b = blockIdx.z;
    int i0 = blockIdx.x * LT;
    int cb = blockIdx.y * LCW;
    int lc = tid * 2;                          // local column pair

    // load state rows [i0-9, i0+41) x [cb, cb+LCW)
#pragma unroll
    for (int r = 0; r < LSROWS; r++) {
        int j = i0 - 9 + r;
        if (j >= 0 && j < SS)
            *(float2*)&st[(size_t)r * LCW + lc] =
                *(const float2*)&src[((size_t)b * SS + j) * HH + cb + lc];
    }
    // fused deg: isq for nodes [i0-9, i0+41)
    if (tid < LSROWS) {
        int n = i0 - 9 + tid;
        float isq = 0.f;
        if (n >= 0 && n < SS) {
            float deg = 0.f;
#pragma unroll
            for (int d = 1; d <= RAD; d++) {
                if (n + d < SS) deg += g_mu[((size_t)b * RAD + (d - 1)) * SS + n];
                if (n >= d)     deg += g_mu[((size_t)b * RAD + (d - 1)) * SS + n - d];
            }
            isq = rsqrtf(fmaxf(deg, 1e-6f));
        }
        isqs[tid] = isq;
    }
    __syncthreads();

    // coefficients for LTROWS tmp rows (clamped je)
    for (int idx = tid; idx < LTROWS * 16; idx += 128) {
        int jl = idx >> 4;
        int k = idx & 15;
        int j = i0 - 1 + jl;
        int je = min(max(j, 0), SS - 1);
        int d = (k >> 1) + 1;
        float c = 0.f;
        if (!(k & 1)) {
            int jn = je + d;
            if (jn < SS)
                c = g_mu[((size_t)b * RAD + (d - 1)) * SS + je] *
                    isqs[je - (i0 - 9)] * isqs[jn - (i0 - 9)];
        } else {
            int jn = je - d;
            if (jn >= 0)
                c = g_mu[((size_t)b * RAD + (d - 1)) * SS + jn] *
                    isqs[je - (i0 - 9)] * isqs[jn - (i0 - 9)];
        }
        cof[idx] = c;
    }
    __syncthreads();
    if (tid < LTROWS) {
        float s = 0.f;
#pragma unroll
        for (int k = 0; k < 16; k++) s += cof[tid * 16 + k];
        csm[tid] = s;
    }
    __syncthreads();

    float2 t0, t1, t2;
#pragma unroll
    for (int jl = 0; jl < LTROWS; jl++) {
        int j = i0 - 1 + jl;
        int je = min(max(j, 0), SS - 1);
        int jloc = je - i0 + 9;
        float2 si = *(const float2*)&st[(size_t)jloc * LCW + lc];
        float cs = csm[jl];
        float2 acc;
        acc.x = cs * si.x; acc.y = cs * si.y;
#pragma unroll
        for (int k = 0; k < 16; k++) {
            float c = cof[jl * 16 + k];
            if (c != 0.f) {
                int d = (k >> 1) + 1;
                int off = (k & 1) ? -d : d;
                float2 sj = *(const float2*)&st[(size_t)(jloc + off) * LCW + lc];
                acc.x = fmaf(-c, sj.x, acc.x);
                acc.y = fmaf(-c, sj.y, acc.y);
            }
        }
        float2 qv = *(const float2*)&g_q[((size_t)b * SS + je) * HH + cb + lc];
        float2 tv;
        tv.x = si.x - eta * (acc.x - qv.x);
        tv.y = si.y - eta * (acc.y - qv.y);
        t0 = t1; t1 = t2; t2 = tv;
        if (jl >= 2) {
            int i = i0 + jl - 2;
            float2 o;
            o.x = t1.x - LAMv * (2.f * t1.x - t0.x - t2.x);
            o.y = t1.y - LAMv * (2.f * t1.y - t0.y - t2.y);
            *(float2*)&dst[((size_t)b * SS + i) * HH + cb + lc] = o;
        }
    }
}

// ---------------------------------------------------------------------------
// Fused final energy: per tile, energy += 0.5 * sum mu_e * ||s_i - s_j||^2.
// (Full-width tile; runs once.)
// ---------------------------------------------------------------------------
#define EROWS 32
#define EDT 24
#define ENERGY_SMEM (EROWS * HH * sizeof(float))

__global__ __launch_bounds__(256) void energy_tiled_kernel(
    const float* __restrict__ src, float* __restrict__ out)
{
    extern __shared__ float sh[];  // EROWS * HH
    int tid = threadIdx.x;
    int b = blockIdx.y;
    int i0 = blockIdx.x * EDT;

#pragma unroll
    for (int r = 0; r < EROWS; r++) {
        int i = i0 + r;
        if (i < SS)
            ((float4*)(sh + (size_t)r * HH))[tid] =
                ((const float4*)(src + ((size_t)b * SS + i) * HH))[tid];
    }
    __syncthreads();

    int w = tid >> 5, lane = tid & 31;
    float wpart = 0.f;
#pragma unroll
    for (int nn = 0; nn < 3; nn++) {
        int ln = w * 3 + nn;
        int i = i0 + ln;
        if (i >= SS) continue;
        const float4* arow = (const float4*)(sh + (size_t)ln * HH);
        float4 a[8];
#pragma unroll
        for (int r = 0; r < 8; r++) a[r] = arow[lane + 32 * r];
#pragma unroll
        for (int d = 1; d <= RAD; d++) {
            if (i + d >= SS) break;
            const float4* crow = (const float4*)(sh + (size_t)(ln + d) * HH);
            float sum = 0.f;
#pragma unroll
            for (int r = 0; r < 8; r++) {
                float4 c = crow[lane + 32 * r];
                float dx = a[r].x - c.x, dy = a[r].y - c.y;
                float dz = a[r].z - c.z, dw = a[r].w - c.w;
                sum += dx*dx + dy*dy + dz*dz + dw*dw;
            }
#pragma unroll
            for (int o = 16; o > 0; o >>= 1)
                sum += __shfl_xor_sync(0xffffffffu, sum, o);
            if (lane == 0)
                wpart += g_mu[((size_t)b * RAD + (d - 1)) * SS + i] * sum;
        }
    }
    __shared__ float red[8];
    if (lane == 0) red[w] = wpart;
    __syncthreads();
    if (tid == 0) {
        float s = 0.f;
#pragma unroll
        for (int ww = 0; ww < 8; ww++) s += red[ww];
        atomicAdd(&out[(size_t)BSH + b], 0.5f * s);
    }
}

// ---------------------------------------------------------------------------
// out = layernorm(final + hidden) * gamma + beta
// ---------------------------------------------------------------------------
__global__ __launch_bounds__(256) void ln_kernel(
    const float* __restrict__ fin,
    const float* __restrict__ hidden,
    const float* __restrict__ gamma, const float* __restrict__ beta,
    float* __restrict__ out)
{
    int i = blockIdx.x, b = blockIdx.y;
    int tid = threadIdx.x;
    size_t base = ((size_t)b * SS + i) * HH + tid * 4;
    float4 s = *(const float4*)&fin[base];
    float4 h = *(const float4*)&hidden[base];
    float4 x;
    x.x = s.x + h.x; x.y = s.y + h.y; x.z = s.z + h.z; x.w = s.w + h.w;
    float sum = x.x + x.y + x.z + x.w;
    float sq  = x.x*x.x + x.y*x.y + x.z*x.z + x.w*x.w;
#pragma unroll
    for (int o = 16; o > 0; o >>= 1) {
        sum += __shfl_xor_sync(0xffffffffu, sum, o);
        sq  += __shfl_xor_sync(0xffffffffu, sq,  o);
    }
    __shared__ float rs[8], rq[8];
    int wid = tid >> 5, lane = tid & 31;
    if (lane == 0) { rs[wid] = sum; rq[wid] = sq; }
    __syncthreads();
    __shared__ float s_mean, s_rstd;
    if (tid == 0) {
        float ts = 0.f, tq = 0.f;
#pragma unroll
        for (int w = 0; w < 8; w++) { ts += rs[w]; tq += rq[w]; }
        float mean = ts / HH;
        float var = tq / HH - mean * mean;
        s_mean = mean;
        s_rstd = rsqrtf(var + 1e-5f);
    }
    __syncthreads();
    float mean = s_mean, rstd = s_rstd;
    int hbase = tid * 4;
    float4 o;
    o.x = (x.x - mean) * rstd * gamma[hbase+0] + beta[hbase+0];
    o.y = (x.y - mean) * rstd * gamma[hbase+1] + beta[hbase+1];
    o.z = (x.z - mean) * rstd * gamma[hbase+2] + beta[hbase+2];
    o.w = (x.w - mean) * rstd * gamma[hbase+3] + beta[hbase+3];
    *(float4*)&out[base] = o;
}

// ---------------------------------------------------------------------------
extern "C" void kernel_launch(void* const* d_in, const int* in_sizes, int n_in,
                              void* d_out, int out_size)
{
    const float* hidden = (const float*)d_in[0];
    const float* Wq = (const float*)d_in[3];
    const float* bq = (const float*)d_in[4];
    const float* W1 = (const float*)d_in[5];
    const float* b1 = (const float*)d_in[6];
    const float* W2 = (const float*)d_in[7];
    const float* b2 = (const float*)d_in[8];
    const float* gamma = (const float*)d_in[9];
    const float* beta  = (const float*)d_in[10];
    float* out = (float*)d_out;

    float *pA = nullptr, *pB = nullptr;
    cudaGetSymbolAddress((void**)&pA, g_stateA);
    cudaGetSymbolAddress((void**)&pB, g_stateB);

    cudaFuncSetAttribute(gemm_tf32_kernel,
                         cudaFuncAttributeMaxDynamicSharedMemorySize, GEMM_SMEM);
    cudaFuncSetAttribute(dots_half_kernel,
                         cudaFuncAttributeMaxDynamicSharedMemorySize, DOTS_SMEM);
    cudaFuncSetAttribute(energy_tiled_kernel,
                         cudaFuncAttributeMaxDynamicSharedMemorySize, ENERGY_SMEM);
    cudaFuncSetAttribute(lapsmooth_kernel,
                         cudaFuncAttributeMaxDynamicSharedMemorySize, LAPS_SMEM);

    gemm_tf32_kernel<<<dim3(HH / TN, (BB * SS) / TM), 256, GEMM_SMEM>>>(hidden, Wq, bq);
    build_tab_kernel<<<(TABD * TABC * 32 + 255) / 256, 256>>>(W1, b1, W2, b2, out);

    // ping-pong: hidden -> A -> B -> A -> B
    const float* srcs[KSTEPS + 1] = { hidden, pA, pB, pA, pB };
    float*       dsts[KSTEPS]     = { pA, pB, pA, pB };

    const int dots_grid = (SS + DT - 1) / DT;   // 86
    float eta = 0.1f;
    for (int step = 0; step < KSTEPS; step++) {
        dots_half_kernel<<<dim3(dots_grid, BB, 2), 256, DOTS_SMEM>>>(srcs[step]);
        mu_lookup_kernel<<<(BB * RAD * SS) / 256, 256>>>();
        lapsmooth_kernel<<<dim3(SS / LT, HH / LCW, BB), 128, LAPS_SMEM>>>(srcs[step], dsts[step], eta);
        eta *= 0.9f;
    }
    energy_tiled_kernel<<<dim3((SS + EDT - 1) / EDT, BB), 256, ENERGY_SMEM>>>(srcs[KSTEPS], out);
    ln_kernel<<<dim3(SS, BB), 256>>>(srcs[KSTEPS], hidden, gamma, beta, out);
}